// round 6
// baseline (speedup 1.0000x reference)
#include <cuda_runtime.h>
#include <math.h>

#define NN 50000
#define EE 800000
#define HCD 128
#define HEADS 4
#define OUTC 64
#define ED 32
#define NEG 0.2f

// ---------------- scratch (device globals) ------------------------------------
__device__ float g_xl1[NN * HCD];
__device__ float g_xr1[NN * HCD];
__device__ float g_h  [NN * HCD];
__device__ float g_xl2[NN * OUTC];
__device__ float g_xr2[NN * OUTC];
__device__ float g_sum1[NN * HCD];    // unnormalized weighted sums (layer 1)
__device__ float g_den1[NN * HEADS];  // softmax denominators (layer 1)
__device__ float g_sum2[NN * OUTC];   // layer 2
__device__ float g_den2[NN];
__device__ int   g_deg[NN];
__device__ int   g_rowptr[NN + 1];
__device__ int   g_cursor[NN];
__device__ int   g_eperm[EE];         // CSR slot -> edge id
__device__ int   g_srcp[EE];          // CSR slot -> src node
__device__ int   g_dstp[EE];          // CSR slot -> dst node
// pre-packed tf32 B-fragments: [kt][ntg][lane]{b0,b1}
__device__ uint2 g_W1p[16 * 32 * 32];
__device__ uint2 g_W2p[16 * 16 * 32];
__device__ uint2 g_We1p[4 * 16 * 32];
__device__ uint2 g_We2p[4 * 8 * 32];

// ---------------- helpers -------------------------------------------------------
__device__ __forceinline__ unsigned tf32_of(float f) {
    unsigned r;
    asm("cvt.rna.tf32.f32 %0, %1;" : "=r"(r) : "f"(f));
    return r;
}
__device__ __forceinline__ void mma_tf32(float* d,
                                         unsigned a0, unsigned a1, unsigned a2, unsigned a3,
                                         unsigned b0, unsigned b1) {
    asm volatile(
        "mma.sync.aligned.m16n8k8.row.col.f32.tf32.tf32.f32 "
        "{%0,%1,%2,%3}, {%4,%5,%6,%7}, {%8,%9}, {%0,%1,%2,%3};"
        : "+f"(d[0]), "+f"(d[1]), "+f"(d[2]), "+f"(d[3])
        : "r"(a0), "r"(a1), "r"(a2), "r"(a3), "r"(b0), "r"(b1));
}
__device__ __forceinline__ void red_add2(float* p, float x, float y) {
    asm volatile("red.global.add.v2.f32 [%0], {%1, %2};" :: "l"(p), "f"(x), "f"(y) : "memory");
}
__device__ __forceinline__ void red_add1(float* p, float x) {
    asm volatile("red.global.add.f32 [%0], %1;" :: "l"(p), "f"(x) : "memory");
}
__device__ __forceinline__ float lrelu(float x) { return x > 0.f ? x : NEG * x; }

// ---------------- weight fragment pre-pack --------------------------------------
__global__ void prepack_kernel(const float* __restrict__ Wl1, const float* __restrict__ Wr1,
                               const float* __restrict__ Wl2, const float* __restrict__ Wr2,
                               const float* __restrict__ We1, const float* __restrict__ We2) {
    int gw = blockIdx.x * 8 + (threadIdx.x >> 5);
    int lane = threadIdx.x & 31, g = lane >> 2, t4 = lane & 3;
    if (gw < 512) {
        int kt = gw >> 5, ntg = gw & 31;
        int c = ntg * 8 + g, k0 = kt * 8 + t4;
        float v0 = (c < 128) ? Wl1[k0 * 128 + c] : Wr1[k0 * 128 + c - 128];
        float v1 = (c < 128) ? Wl1[(k0 + 4) * 128 + c] : Wr1[(k0 + 4) * 128 + c - 128];
        g_W1p[(kt * 32 + ntg) * 32 + lane] = make_uint2(tf32_of(v0), tf32_of(v1));
    } else if (gw < 768) {
        int r = gw - 512;
        int kt = r >> 4, ntg = r & 15;
        int c = ntg * 8 + g, k0 = kt * 8 + t4;
        float v0 = (c < 64) ? Wl2[k0 * 64 + c] : Wr2[k0 * 64 + c - 64];
        float v1 = (c < 64) ? Wl2[(k0 + 4) * 64 + c] : Wr2[(k0 + 4) * 64 + c - 64];
        g_W2p[(kt * 16 + ntg) * 32 + lane] = make_uint2(tf32_of(v0), tf32_of(v1));
    } else if (gw < 832) {
        int r = gw - 768;
        int kt = r >> 4, ntg = r & 15;
        int c = ntg * 8 + g, k0 = kt * 8 + t4;
        g_We1p[(kt * 16 + ntg) * 32 + lane] =
            make_uint2(tf32_of(We1[k0 * 128 + c]), tf32_of(We1[(k0 + 4) * 128 + c]));
    } else if (gw < 864) {
        int r = gw - 832;
        int kt = r >> 3, ntg = r & 7;
        int c = ntg * 8 + g, k0 = kt * 8 + t4;
        g_We2p[(kt * 8 + ntg) * 32 + lane] =
            make_uint2(tf32_of(We2[k0 * 64 + c]), tf32_of(We2[(k0 + 4) * 64 + c]));
    }
}

// ---------------- CSR build -----------------------------------------------------
__global__ void csr_count_kernel(const int* __restrict__ dst) {
    int e = blockIdx.x * blockDim.x + threadIdx.x;
    if (e < EE) atomicAdd(&g_deg[dst[e]], 1);
}

__global__ void scan_kernel() {
    __shared__ int wtot[32];
    __shared__ int carry_sm;
    int t = threadIdx.x, lane = t & 31, wid = t >> 5;
    if (t == 0) carry_sm = 0;
    __syncthreads();
    for (int base = 0; base < NN; base += 4096) {
        int carry = carry_sm;
        int idx = base + t * 4;
        int4 v = make_int4(0, 0, 0, 0);
        if (idx + 3 < NN) v = *(const int4*)&g_deg[idx];
        else {
            if (idx     < NN) v.x = g_deg[idx];
            if (idx + 1 < NN) v.y = g_deg[idx + 1];
            if (idx + 2 < NN) v.z = g_deg[idx + 2];
        }
        int s1 = v.x + v.y, s2 = s1 + v.z, tsum = s2 + v.w;
        int sc = tsum;
        #pragma unroll
        for (int off = 1; off < 32; off <<= 1) {
            int u = __shfl_up_sync(0xffffffffu, sc, off);
            if (lane >= off) sc += u;
        }
        if (lane == 31) wtot[wid] = sc;
        __syncthreads();
        if (wid == 0) {
            int wv = wtot[lane];
            int ws = wv;
            #pragma unroll
            for (int off = 1; off < 32; off <<= 1) {
                int u = __shfl_up_sync(0xffffffffu, ws, off);
                if (lane >= off) ws += u;
            }
            wtot[lane] = ws - wv;
        }
        __syncthreads();
        int off0 = carry + wtot[wid] + (sc - tsum);
        if (idx     < NN) g_cursor[idx]     = off0;
        if (idx + 1 < NN) g_cursor[idx + 1] = off0 + v.x;
        if (idx + 2 < NN) g_cursor[idx + 2] = off0 + s1;
        if (idx + 3 < NN) g_cursor[idx + 3] = off0 + s2;
        if (t == 1023) carry_sm = carry + wtot[31] + sc;
        __syncthreads();
    }
}

__global__ void csr_fill_kernel(const int* __restrict__ src, const int* __restrict__ dst) {
    int e = blockIdx.x * blockDim.x + threadIdx.x;
    if (e < EE) {
        int d = dst[e];
        int pos = atomicAdd(&g_cursor[d], 1);
        g_eperm[pos] = e;
        g_srcp[pos] = src[e];
        g_dstp[pos] = d;
    }
}

// ---------------- node transform: direct-LDG tf32 MMA ---------------------------
template<int OUTD, int TC>
__global__ __launch_bounds__(256) void transform_direct(
    const float* __restrict__ x, const uint2* __restrict__ Wp,
    const float* __restrict__ bl, const float* __restrict__ br,
    float* __restrict__ xl, float* __restrict__ xr) {
    constexpr int NTT = TC / 8;
    int tid = threadIdx.x;
    int w = tid >> 5, lane = tid & 31, g = lane >> 2, t4 = lane & 3;
    int mrow = w & 3, ncol = w >> 2;
    int node0 = blockIdx.x * 128 + mrow * 32;
    int ntbase = blockIdx.y * 16 + ncol * 8;

    float acc[2][8][4];
    #pragma unroll
    for (int mt = 0; mt < 2; mt++)
        #pragma unroll
        for (int nt = 0; nt < 8; nt++)
            #pragma unroll
            for (int i = 0; i < 4; i++) acc[mt][nt][i] = 0.f;

    #pragma unroll 4
    for (int kt = 0; kt < 16; kt++) {
        unsigned a[2][4];
        #pragma unroll
        for (int mt = 0; mt < 2; mt++) {
            int r0 = node0 + mt * 16 + g;
            int r1 = r0 + 8;
            if (r0 >= NN) r0 = NN - 1;
            if (r1 >= NN) r1 = NN - 1;
            const float* p0 = x + r0 * 128 + kt * 8 + t4;
            const float* p1 = x + r1 * 128 + kt * 8 + t4;
            a[mt][0] = tf32_of(__ldg(p0));
            a[mt][1] = tf32_of(__ldg(p1));
            a[mt][2] = tf32_of(__ldg(p0 + 4));
            a[mt][3] = tf32_of(__ldg(p1 + 4));
        }
        const uint2* wrow = Wp + (kt * NTT + ntbase) * 32 + lane;
        #pragma unroll
        for (int nt = 0; nt < 8; nt++) {
            uint2 b = __ldg(wrow + nt * 32);
            mma_tf32(acc[0][nt], a[0][0], a[0][1], a[0][2], a[0][3], b.x, b.y);
            mma_tf32(acc[1][nt], a[1][0], a[1][1], a[1][2], a[1][3], b.x, b.y);
        }
    }

    #pragma unroll
    for (int nt = 0; nt < 8; nt++) {
        int c = (ntbase + nt) * 8 + t4 * 2;
        const float* bp; float* op; int cc;
        if (c < OUTD) { cc = c; bp = bl; op = xl; }
        else          { cc = c - OUTD; bp = br; op = xr; }
        float2 bv = *(const float2*)&bp[cc];
        #pragma unroll
        for (int mt = 0; mt < 2; mt++) {
            int n0v = node0 + mt * 16 + g;
            if (n0v < NN)
                *(float2*)&op[n0v * OUTD + cc] =
                    make_float2(acc[mt][nt][0] + bv.x, acc[mt][nt][1] + bv.y);
            int n1v = n0v + 8;
            if (n1v < NN)
                *(float2*)&op[n1v * OUTD + cc] =
                    make_float2(acc[mt][nt][2] + bv.x, acc[mt][nt][3] + bv.y);
        }
    }
}

// ---------------- layer-1 fused logits + softmax-accumulate ---------------------
// Warp handles 16 CSR slots: m16(edges) x n128(channels), K=32. After computing
// per-edge per-head logits, accumulates exp(a)*xl[src] and exp(a) into g_sum1/g_den1.
__global__ __launch_bounds__(256) void edge_fused1(
    const float* __restrict__ ea, const float* __restrict__ att) {
    int tid = threadIdx.x;
    int w = tid >> 5, lane = tid & 31, g = lane >> 2, t4 = lane & 3;
    int sbase = blockIdx.x * 128 + w * 16;

    int e0 = g_eperm[sbase + g];
    int e1 = g_eperm[sbase + 8 + g];

    float d[16][4];
    #pragma unroll
    for (int nt = 0; nt < 16; nt++)
        #pragma unroll
        for (int i = 0; i < 4; i++) d[nt][i] = 0.f;

    #pragma unroll
    for (int kt = 0; kt < 4; kt++) {
        const float* p0 = ea + e0 * 32 + kt * 8 + t4;
        const float* p1 = ea + e1 * 32 + kt * 8 + t4;
        unsigned a0 = tf32_of(__ldg(p0));
        unsigned a1 = tf32_of(__ldg(p1));
        unsigned a2 = tf32_of(__ldg(p0 + 4));
        unsigned a3 = tf32_of(__ldg(p1 + 4));
        const uint2* wrow = g_We1p + (kt * 16) * 32 + lane;
        #pragma unroll
        for (int nt = 0; nt < 16; nt++) {
            uint2 b = __ldg(wrow + nt * 32);
            mma_tf32(d[nt], a0, a1, a2, a3, b.x, b.y);
        }
    }

    #pragma unroll
    for (int rsel = 0; rsel < 2; rsel++) {
        int slot = sbase + g + 8 * rsel;
        int s = g_srcp[slot], dd = g_dstp[slot];
        const float* xlr = g_xl1 + s * HCD;
        const float* xrr = g_xr1 + dd * HCD;
        float ph0 = 0.f, ph1 = 0.f, ph2 = 0.f, ph3 = 0.f;
        #pragma unroll
        for (int nt = 0; nt < 16; nt++) {
            int c = nt * 8 + t4 * 2;
            float2 xlv = *(const float2*)&xlr[c];
            float2 xrv = *(const float2*)&xrr[c];
            float2 atv = *(const float2*)&att[c];
            float v0 = d[nt][rsel * 2]     + xlv.x + xrv.x;
            float v1 = d[nt][rsel * 2 + 1] + xlv.y + xrv.y;
            float p = lrelu(v0) * atv.x + lrelu(v1) * atv.y;
            if      (nt < 4)  ph0 += p;
            else if (nt < 8)  ph1 += p;
            else if (nt < 12) ph2 += p;
            else              ph3 += p;
        }
        ph0 += __shfl_xor_sync(0xffffffffu, ph0, 1); ph0 += __shfl_xor_sync(0xffffffffu, ph0, 2);
        ph1 += __shfl_xor_sync(0xffffffffu, ph1, 1); ph1 += __shfl_xor_sync(0xffffffffu, ph1, 2);
        ph2 += __shfl_xor_sync(0xffffffffu, ph2, 1); ph2 += __shfl_xor_sync(0xffffffffu, ph2, 2);
        ph3 += __shfl_xor_sync(0xffffffffu, ph3, 1); ph3 += __shfl_xor_sync(0xffffffffu, ph3, 2);
        float wgt[4];
        wgt[0] = __expf(ph0); wgt[1] = __expf(ph1);
        wgt[2] = __expf(ph2); wgt[3] = __expf(ph3);
        // denominator: lane t4 adds head t4's weight
        red_add1(&g_den1[dd * HEADS + t4], wgt[t4]);
        // weighted sum of source features
        float* sp = g_sum1 + dd * HCD;
        #pragma unroll
        for (int nt = 0; nt < 16; nt++) {
            int c = nt * 8 + t4 * 2;
            float2 xlv = *(const float2*)&xlr[c];
            float ww = wgt[nt >> 2];
            red_add2(sp + c, ww * xlv.x, ww * xlv.y);
        }
    }
}

// ---------------- layer-1 normalize + bias + elu --------------------------------
__global__ void normalize1_kernel(const float* __restrict__ bias) {
    int idx = blockIdx.x * blockDim.x + threadIdx.x;   // one float4 per thread
    if (idx >= NN * 32) return;
    int node = idx >> 5;
    int c0 = (idx & 31) * 4;
    float4 s = *(const float4*)&g_sum1[node * HCD + c0];
    float den = g_den1[node * HEADS + (c0 >> 5)] + 1e-16f;
    float inv = 1.f / den;
    float4 bv = *(const float4*)&bias[c0];
    float o0 = s.x * inv + bv.x;
    float o1 = s.y * inv + bv.y;
    float o2 = s.z * inv + bv.z;
    float o3 = s.w * inv + bv.w;
    o0 = o0 > 0.f ? o0 : expm1f(o0);
    o1 = o1 > 0.f ? o1 : expm1f(o1);
    o2 = o2 > 0.f ? o2 : expm1f(o2);
    o3 = o3 > 0.f ? o3 : expm1f(o3);
    *(float4*)&g_h[node * HCD + c0] = make_float4(o0, o1, o2, o3);
}

// ---------------- layer-2 fused logits + softmax-accumulate ---------------------
__global__ __launch_bounds__(256) void edge_fused2(
    const float* __restrict__ ea, const float* __restrict__ att) {
    int tid = threadIdx.x;
    int w = tid >> 5, lane = tid & 31, g = lane >> 2, t4 = lane & 3;
    int sbase = blockIdx.x * 128 + w * 16;

    int e0 = g_eperm[sbase + g];
    int e1 = g_eperm[sbase + 8 + g];

    float d[8][4];
    #pragma unroll
    for (int nt = 0; nt < 8; nt++)
        #pragma unroll
        for (int i = 0; i < 4; i++) d[nt][i] = 0.f;

    #pragma unroll
    for (int kt = 0; kt < 4; kt++) {
        const float* p0 = ea + e0 * 32 + kt * 8 + t4;
        const float* p1 = ea + e1 * 32 + kt * 8 + t4;
        unsigned a0 = tf32_of(__ldg(p0));
        unsigned a1 = tf32_of(__ldg(p1));
        unsigned a2 = tf32_of(__ldg(p0 + 4));
        unsigned a3 = tf32_of(__ldg(p1 + 4));
        const uint2* wrow = g_We2p + (kt * 8) * 32 + lane;
        #pragma unroll
        for (int nt = 0; nt < 8; nt++) {
            uint2 b = __ldg(wrow + nt * 32);
            mma_tf32(d[nt], a0, a1, a2, a3, b.x, b.y);
        }
    }

    #pragma unroll
    for (int rsel = 0; rsel < 2; rsel++) {
        int slot = sbase + g + 8 * rsel;
        int s = g_srcp[slot], dd = g_dstp[slot];
        const float* xlr = g_xl2 + s * OUTC;
        const float* xrr = g_xr2 + dd * OUTC;
        float ps = 0.f;
        #pragma unroll
        for (int nt = 0; nt < 8; nt++) {
            int c = nt * 8 + t4 * 2;
            float2 xlv = *(const float2*)&xlr[c];
            float2 xrv = *(const float2*)&xrr[c];
            float2 atv = *(const float2*)&att[c];
            float v0 = d[nt][rsel * 2]     + xlv.x + xrv.x;
            float v1 = d[nt][rsel * 2 + 1] + xlv.y + xrv.y;
            ps += lrelu(v0) * atv.x + lrelu(v1) * atv.y;
        }
        ps += __shfl_xor_sync(0xffffffffu, ps, 1);
        ps += __shfl_xor_sync(0xffffffffu, ps, 2);
        float wgt = __expf(ps);
        if (t4 == 0) red_add1(&g_den2[dd], wgt);
        float* sp = g_sum2 + dd * OUTC;
        #pragma unroll
        for (int nt = 0; nt < 8; nt++) {
            int c = nt * 8 + t4 * 2;
            float2 xlv = *(const float2*)&xlr[c];
            red_add2(sp + c, wgt * xlv.x, wgt * xlv.y);
        }
    }
}

// ---------------- layer-2 normalize + bias --------------------------------------
__global__ void normalize2_kernel(const float* __restrict__ bias, float* __restrict__ out) {
    int idx = blockIdx.x * blockDim.x + threadIdx.x;   // one float2 per thread
    if (idx >= NN * 32) return;
    int node = idx >> 5;
    int c0 = (idx & 31) * 2;
    float2 s = *(const float2*)&g_sum2[node * OUTC + c0];
    float inv = 1.f / (g_den2[node] + 1e-16f);
    float o0 = s.x * inv + bias[c0];
    float o1 = s.y * inv + bias[c0 + 1];
    *(float2*)&out[node * OUTC + c0] = make_float2(o0, o1);
}

// ---------------- host launcher ---------------------------------------------------
extern "C" void kernel_launch(void* const* d_in, const int* in_sizes, int n_in,
                              void* d_out, int out_size) {
    const float* x    = (const float*)d_in[0];
    const int*   ei   = (const int*)  d_in[1];
    const float* ea   = (const float*)d_in[2];
    const float* Wl1  = (const float*)d_in[3];
    const float* bl1  = (const float*)d_in[4];
    const float* Wr1  = (const float*)d_in[5];
    const float* br1  = (const float*)d_in[6];
    const float* We1  = (const float*)d_in[7];
    const float* att1 = (const float*)d_in[8];
    const float* bias1= (const float*)d_in[9];
    const float* Wl2  = (const float*)d_in[10];
    const float* bl2  = (const float*)d_in[11];
    const float* Wr2  = (const float*)d_in[12];
    const float* br2  = (const float*)d_in[13];
    const float* We2  = (const float*)d_in[14];
    const float* att2 = (const float*)d_in[15];
    const float* bias2= (const float*)d_in[16];

    const int* src = ei;
    const int* dst = ei + EE;

    void *p_xl1, *p_xr1, *p_h, *p_xl2, *p_xr2, *p_deg, *p_W1p, *p_W2p;
    void *p_sum1, *p_den1, *p_sum2, *p_den2;
    cudaGetSymbolAddress(&p_xl1, g_xl1);
    cudaGetSymbolAddress(&p_xr1, g_xr1);
    cudaGetSymbolAddress(&p_h,   g_h);
    cudaGetSymbolAddress(&p_xl2, g_xl2);
    cudaGetSymbolAddress(&p_xr2, g_xr2);
    cudaGetSymbolAddress(&p_deg, g_deg);
    cudaGetSymbolAddress(&p_W1p, g_W1p);
    cudaGetSymbolAddress(&p_W2p, g_W2p);
    cudaGetSymbolAddress(&p_sum1, g_sum1);
    cudaGetSymbolAddress(&p_den1, g_den1);
    cudaGetSymbolAddress(&p_sum2, g_sum2);
    cudaGetSymbolAddress(&p_den2, g_den2);

    // zero accumulators + degree
    cudaMemsetAsync(p_deg, 0, NN * sizeof(int));
    cudaMemsetAsync(p_sum1, 0, NN * HCD * sizeof(float));
    cudaMemsetAsync(p_den1, 0, NN * HEADS * sizeof(float));
    cudaMemsetAsync(p_sum2, 0, NN * OUTC * sizeof(float));
    cudaMemsetAsync(p_den2, 0, NN * sizeof(float));

    // weight pre-pack + CSR
    prepack_kernel<<<108, 256>>>(Wl1, Wr1, Wl2, Wr2, We1, We2);
    csr_count_kernel<<<(EE + 255) / 256, 256>>>(dst);
    scan_kernel<<<1, 1024>>>();
    csr_fill_kernel<<<(EE + 255) / 256, 256>>>(src, dst);

    // layer 1
    transform_direct<HCD, 256><<<dim3((NN + 127) / 128, 2), 256>>>(
        x, (const uint2*)p_W1p, bl1, br1, (float*)p_xl1, (float*)p_xr1);
    edge_fused1<<<EE / 128, 256>>>(ea, att1);
    normalize1_kernel<<<(NN * 32 + 255) / 256, 256>>>(bias1);

    // layer 2
    transform_direct<OUTC, 128><<<dim3((NN + 127) / 128, 1), 256>>>(
        (const float*)p_h, (const uint2*)p_W2p, bl2, br2, (float*)p_xl2, (float*)p_xr2);
    edge_fused2<<<EE / 128, 256>>>(ea, att2);
    normalize2_kernel<<<(NN * 32 + 255) / 256, 256>>>(bias2, (float*)d_out);
}

// round 7
// speedup vs baseline: 1.3159x; 1.3159x over previous
#include <cuda_runtime.h>
#include <math.h>

#define NN 50000
#define EE 800000
#define HCD 128
#define HEADS 4
#define OUTC 64
#define ED 32
#define NEG 0.2f

// ---------------- scratch (device globals) ------------------------------------
__device__ float g_xl1[NN * HCD];
__device__ float g_xr1[NN * HCD];
__device__ float g_h  [NN * HCD];
__device__ float g_xl2[NN * OUTC];
__device__ float g_xr2[NN * OUTC];
__device__ float g_a1p[EE * HEADS];   // logits layer1, CSR slot order, [slot][head]
__device__ float g_a2p[EE];           // logits layer2, CSR slot order
__device__ int   g_deg[NN];
__device__ int   g_rowptr[NN + 1];
__device__ int   g_cursor[NN];
__device__ int4  g_sde[EE];           // CSR slot -> {src, dst, edge, 0}
// pre-packed tf32 B-fragments: [kt][ntg][lane]{b0,b1}
__device__ uint2 g_W1p[16 * 32 * 32];
__device__ uint2 g_W2p[16 * 16 * 32];
__device__ uint2 g_We1p[4 * 16 * 32];
__device__ uint2 g_We2p[4 * 8 * 32];

// ---------------- helpers -------------------------------------------------------
__device__ __forceinline__ unsigned tf32_of(float f) {
    unsigned r;
    asm("cvt.rna.tf32.f32 %0, %1;" : "=r"(r) : "f"(f));
    return r;
}
__device__ __forceinline__ void mma_tf32(float* d,
                                         unsigned a0, unsigned a1, unsigned a2, unsigned a3,
                                         unsigned b0, unsigned b1) {
    asm volatile(
        "mma.sync.aligned.m16n8k8.row.col.f32.tf32.tf32.f32 "
        "{%0,%1,%2,%3}, {%4,%5,%6,%7}, {%8,%9}, {%0,%1,%2,%3};"
        : "+f"(d[0]), "+f"(d[1]), "+f"(d[2]), "+f"(d[3])
        : "r"(a0), "r"(a1), "r"(a2), "r"(a3), "r"(b0), "r"(b1));
}
__device__ __forceinline__ float lrelu(float x) { return x > 0.f ? x : NEG * x; }

// ---------------- weight fragment pre-pack --------------------------------------
__global__ void prepack_kernel(const float* __restrict__ Wl1, const float* __restrict__ Wr1,
                               const float* __restrict__ Wl2, const float* __restrict__ Wr2,
                               const float* __restrict__ We1, const float* __restrict__ We2) {
    int gw = blockIdx.x * 8 + (threadIdx.x >> 5);
    int lane = threadIdx.x & 31, g = lane >> 2, t4 = lane & 3;
    if (gw < 512) {
        int kt = gw >> 5, ntg = gw & 31;
        int c = ntg * 8 + g, k0 = kt * 8 + t4;
        float v0 = (c < 128) ? Wl1[k0 * 128 + c] : Wr1[k0 * 128 + c - 128];
        float v1 = (c < 128) ? Wl1[(k0 + 4) * 128 + c] : Wr1[(k0 + 4) * 128 + c - 128];
        g_W1p[(kt * 32 + ntg) * 32 + lane] = make_uint2(tf32_of(v0), tf32_of(v1));
    } else if (gw < 768) {
        int r = gw - 512;
        int kt = r >> 4, ntg = r & 15;
        int c = ntg * 8 + g, k0 = kt * 8 + t4;
        float v0 = (c < 64) ? Wl2[k0 * 64 + c] : Wr2[k0 * 64 + c - 64];
        float v1 = (c < 64) ? Wl2[(k0 + 4) * 64 + c] : Wr2[(k0 + 4) * 64 + c - 64];
        g_W2p[(kt * 16 + ntg) * 32 + lane] = make_uint2(tf32_of(v0), tf32_of(v1));
    } else if (gw < 832) {
        int r = gw - 768;
        int kt = r >> 4, ntg = r & 15;
        int c = ntg * 8 + g, k0 = kt * 8 + t4;
        g_We1p[(kt * 16 + ntg) * 32 + lane] =
            make_uint2(tf32_of(We1[k0 * 128 + c]), tf32_of(We1[(k0 + 4) * 128 + c]));
    } else if (gw < 864) {
        int r = gw - 832;
        int kt = r >> 3, ntg = r & 7;
        int c = ntg * 8 + g, k0 = kt * 8 + t4;
        g_We2p[(kt * 8 + ntg) * 32 + lane] =
            make_uint2(tf32_of(We2[k0 * 64 + c]), tf32_of(We2[(k0 + 4) * 64 + c]));
    }
}

// ---------------- CSR build -----------------------------------------------------
__global__ void csr_count_kernel(const int* __restrict__ dst) {
    int t = blockIdx.x * blockDim.x + threadIdx.x;
    int e4 = t * 4;
    if (e4 < EE) {
        int4 d = *(const int4*)&dst[e4];
        atomicAdd(&g_deg[d.x], 1);
        atomicAdd(&g_deg[d.y], 1);
        atomicAdd(&g_deg[d.z], 1);
        atomicAdd(&g_deg[d.w], 1);
    }
}

__global__ void scan_kernel() {
    __shared__ int wtot[32];
    __shared__ int carry_sm;
    int t = threadIdx.x, lane = t & 31, wid = t >> 5;
    if (t == 0) carry_sm = 0;
    __syncthreads();
    for (int base = 0; base < NN; base += 4096) {
        int carry = carry_sm;
        int idx = base + t * 4;
        int4 v = make_int4(0, 0, 0, 0);
        if (idx + 3 < NN) v = *(const int4*)&g_deg[idx];
        else {
            if (idx     < NN) v.x = g_deg[idx];
            if (idx + 1 < NN) v.y = g_deg[idx + 1];
            if (idx + 2 < NN) v.z = g_deg[idx + 2];
        }
        int s1 = v.x + v.y, s2 = s1 + v.z, tsum = s2 + v.w;
        int sc = tsum;
        #pragma unroll
        for (int off = 1; off < 32; off <<= 1) {
            int u = __shfl_up_sync(0xffffffffu, sc, off);
            if (lane >= off) sc += u;
        }
        if (lane == 31) wtot[wid] = sc;
        __syncthreads();
        if (wid == 0) {
            int wv = wtot[lane];
            int ws = wv;
            #pragma unroll
            for (int off = 1; off < 32; off <<= 1) {
                int u = __shfl_up_sync(0xffffffffu, ws, off);
                if (lane >= off) ws += u;
            }
            wtot[lane] = ws - wv;
        }
        __syncthreads();
        int off0 = carry + wtot[wid] + (sc - tsum);
        if (idx     < NN) { g_rowptr[idx]     = off0;        g_cursor[idx]     = off0; }
        if (idx + 1 < NN) { int o = off0 + v.x; g_rowptr[idx + 1] = o; g_cursor[idx + 1] = o; }
        if (idx + 2 < NN) { int o = off0 + s1;  g_rowptr[idx + 2] = o; g_cursor[idx + 2] = o; }
        if (idx + 3 < NN) { int o = off0 + s2;  g_rowptr[idx + 3] = o; g_cursor[idx + 3] = o; }
        if (t == 1023) carry_sm = carry + wtot[31] + sc;
        __syncthreads();
    }
    if (t == 0) g_rowptr[NN] = EE;
}

__global__ void csr_fill_kernel(const int* __restrict__ src, const int* __restrict__ dst) {
    int e = blockIdx.x * blockDim.x + threadIdx.x;
    if (e < EE) {
        int d = dst[e];
        int pos = atomicAdd(&g_cursor[d], 1);
        g_sde[pos] = make_int4(src[e], d, e, 0);
    }
}

// ---------------- node transform: direct-LDG tf32 MMA ---------------------------
template<int OUTD, int TC>
__global__ __launch_bounds__(256) void transform_direct(
    const float* __restrict__ x, const uint2* __restrict__ Wp,
    const float* __restrict__ bl, const float* __restrict__ br,
    float* __restrict__ xl, float* __restrict__ xr) {
    constexpr int NTT = TC / 8;
    int tid = threadIdx.x;
    int w = tid >> 5, lane = tid & 31, g = lane >> 2, t4 = lane & 3;
    int mrow = w & 3, ncol = w >> 2;
    int node0 = blockIdx.x * 128 + mrow * 32;
    int ntbase = blockIdx.y * 16 + ncol * 8;

    float acc[2][8][4];
    #pragma unroll
    for (int mt = 0; mt < 2; mt++)
        #pragma unroll
        for (int nt = 0; nt < 8; nt++)
            #pragma unroll
            for (int i = 0; i < 4; i++) acc[mt][nt][i] = 0.f;

    #pragma unroll 4
    for (int kt = 0; kt < 16; kt++) {
        unsigned a[2][4];
        #pragma unroll
        for (int mt = 0; mt < 2; mt++) {
            int r0 = node0 + mt * 16 + g;
            int r1 = r0 + 8;
            if (r0 >= NN) r0 = NN - 1;
            if (r1 >= NN) r1 = NN - 1;
            const float* p0 = x + r0 * 128 + kt * 8 + t4;
            const float* p1 = x + r1 * 128 + kt * 8 + t4;
            a[mt][0] = tf32_of(__ldg(p0));
            a[mt][1] = tf32_of(__ldg(p1));
            a[mt][2] = tf32_of(__ldg(p0 + 4));
            a[mt][3] = tf32_of(__ldg(p1 + 4));
        }
        const uint2* wrow = Wp + (kt * NTT + ntbase) * 32 + lane;
        #pragma unroll
        for (int nt = 0; nt < 8; nt++) {
            uint2 b = __ldg(wrow + nt * 32);
            mma_tf32(acc[0][nt], a[0][0], a[0][1], a[0][2], a[0][3], b.x, b.y);
            mma_tf32(acc[1][nt], a[1][0], a[1][1], a[1][2], a[1][3], b.x, b.y);
        }
    }

    #pragma unroll
    for (int nt = 0; nt < 8; nt++) {
        int c = (ntbase + nt) * 8 + t4 * 2;
        const float* bp; float* op; int cc;
        if (c < OUTD) { cc = c; bp = bl; op = xl; }
        else          { cc = c - OUTD; bp = br; op = xr; }
        float2 bv = *(const float2*)&bp[cc];
        #pragma unroll
        for (int mt = 0; mt < 2; mt++) {
            int n0v = node0 + mt * 16 + g;
            if (n0v < NN)
                *(float2*)&op[n0v * OUTD + cc] =
                    make_float2(acc[mt][nt][0] + bv.x, acc[mt][nt][1] + bv.y);
            int n1v = n0v + 8;
            if (n1v < NN)
                *(float2*)&op[n1v * OUTD + cc] =
                    make_float2(acc[mt][nt][2] + bv.x, acc[mt][nt][3] + bv.y);
        }
    }
}

// ---------------- layer-1 edge logits: CSR-ordered tf32 MMA ---------------------
__global__ __launch_bounds__(256) void edge_logits1_direct(
    const float* __restrict__ ea, const float* __restrict__ att) {
    int tid = threadIdx.x;
    int w = tid >> 5, lane = tid & 31, g = lane >> 2, t4 = lane & 3;
    int sbase = blockIdx.x * 128 + w * 16;

    int4 sd0 = g_sde[sbase + g];
    int4 sd1 = g_sde[sbase + 8 + g];
    int e0 = sd0.z, e1 = sd1.z;

    float d[16][4];
    #pragma unroll
    for (int nt = 0; nt < 16; nt++)
        #pragma unroll
        for (int i = 0; i < 4; i++) d[nt][i] = 0.f;

    #pragma unroll
    for (int kt = 0; kt < 4; kt++) {
        const float* p0 = ea + e0 * 32 + kt * 8 + t4;
        const float* p1 = ea + e1 * 32 + kt * 8 + t4;
        unsigned a0 = tf32_of(__ldg(p0));
        unsigned a1 = tf32_of(__ldg(p1));
        unsigned a2 = tf32_of(__ldg(p0 + 4));
        unsigned a3 = tf32_of(__ldg(p1 + 4));
        const uint2* wrow = g_We1p + (kt * 16) * 32 + lane;
        #pragma unroll
        for (int nt = 0; nt < 16; nt++) {
            uint2 b = __ldg(wrow + nt * 32);
            mma_tf32(d[nt], a0, a1, a2, a3, b.x, b.y);
        }
    }

    #pragma unroll
    for (int rsel = 0; rsel < 2; rsel++) {
        int slot = (rsel == 0) ? (sbase + g) : (sbase + 8 + g);
        int s  = (rsel == 0) ? sd0.x : sd1.x;
        int dd = (rsel == 0) ? sd0.y : sd1.y;
        const float* xlr = g_xl1 + s * HCD;
        const float* xrr = g_xr1 + dd * HCD;
        float ph0 = 0.f, ph1 = 0.f, ph2 = 0.f, ph3 = 0.f;
        #pragma unroll
        for (int nt = 0; nt < 16; nt++) {
            int c = nt * 8 + t4 * 2;
            float2 xlv = *(const float2*)&xlr[c];
            float2 xrv = *(const float2*)&xrr[c];
            float2 atv = *(const float2*)&att[c];
            float v0 = d[nt][rsel * 2]     + xlv.x + xrv.x;
            float v1 = d[nt][rsel * 2 + 1] + xlv.y + xrv.y;
            float p = lrelu(v0) * atv.x + lrelu(v1) * atv.y;
            if      (nt < 4)  ph0 += p;
            else if (nt < 8)  ph1 += p;
            else if (nt < 12) ph2 += p;
            else              ph3 += p;
        }
        ph0 += __shfl_xor_sync(0xffffffffu, ph0, 1); ph0 += __shfl_xor_sync(0xffffffffu, ph0, 2);
        ph1 += __shfl_xor_sync(0xffffffffu, ph1, 1); ph1 += __shfl_xor_sync(0xffffffffu, ph1, 2);
        ph2 += __shfl_xor_sync(0xffffffffu, ph2, 1); ph2 += __shfl_xor_sync(0xffffffffu, ph2, 2);
        ph3 += __shfl_xor_sync(0xffffffffu, ph3, 1); ph3 += __shfl_xor_sync(0xffffffffu, ph3, 2);
        float myv = (t4 == 0) ? ph0 : (t4 == 1) ? ph1 : (t4 == 2) ? ph2 : ph3;
        g_a1p[slot * HEADS + t4] = myv;
    }
}

// ---------------- layer-2 edge logits: CSR-ordered tf32 MMA ---------------------
__global__ __launch_bounds__(256) void edge_logits2_direct(
    const float* __restrict__ ea, const float* __restrict__ att) {
    int tid = threadIdx.x;
    int w = tid >> 5, lane = tid & 31, g = lane >> 2, t4 = lane & 3;
    int sbase = blockIdx.x * 128 + w * 16;

    int4 sd0 = g_sde[sbase + g];
    int4 sd1 = g_sde[sbase + 8 + g];
    int e0 = sd0.z, e1 = sd1.z;

    float d[8][4];
    #pragma unroll
    for (int nt = 0; nt < 8; nt++)
        #pragma unroll
        for (int i = 0; i < 4; i++) d[nt][i] = 0.f;

    #pragma unroll
    for (int kt = 0; kt < 4; kt++) {
        const float* p0 = ea + e0 * 32 + kt * 8 + t4;
        const float* p1 = ea + e1 * 32 + kt * 8 + t4;
        unsigned a0 = tf32_of(__ldg(p0));
        unsigned a1 = tf32_of(__ldg(p1));
        unsigned a2 = tf32_of(__ldg(p0 + 4));
        unsigned a3 = tf32_of(__ldg(p1 + 4));
        const uint2* wrow = g_We2p + (kt * 8) * 32 + lane;
        #pragma unroll
        for (int nt = 0; nt < 8; nt++) {
            uint2 b = __ldg(wrow + nt * 32);
            mma_tf32(d[nt], a0, a1, a2, a3, b.x, b.y);
        }
    }

    #pragma unroll
    for (int rsel = 0; rsel < 2; rsel++) {
        int slot = (rsel == 0) ? (sbase + g) : (sbase + 8 + g);
        int s  = (rsel == 0) ? sd0.x : sd1.x;
        int dd = (rsel == 0) ? sd0.y : sd1.y;
        const float* xlr = g_xl2 + s * OUTC;
        const float* xrr = g_xr2 + dd * OUTC;
        float ps = 0.f;
        #pragma unroll
        for (int nt = 0; nt < 8; nt++) {
            int c = nt * 8 + t4 * 2;
            float2 xlv = *(const float2*)&xlr[c];
            float2 xrv = *(const float2*)&xrr[c];
            float2 atv = *(const float2*)&att[c];
            float v0 = d[nt][rsel * 2]     + xlv.x + xrv.x;
            float v1 = d[nt][rsel * 2 + 1] + xlv.y + xrv.y;
            ps += lrelu(v0) * atv.x + lrelu(v1) * atv.y;
        }
        ps += __shfl_xor_sync(0xffffffffu, ps, 1);
        ps += __shfl_xor_sync(0xffffffffu, ps, 2);
        if (t4 == 0) g_a2p[slot] = ps;
    }
}

// ---------------- layer-1 softmax (no max-sub) + aggregate + bias + elu ---------
__global__ void aggregate1_kernel(const float* __restrict__ bias) {
    int i = (blockIdx.x * blockDim.x + threadIdx.x) >> 5;
    int lane = threadIdx.x & 31;
    if (i >= NN) return;
    int start = g_rowptr[i], end = g_rowptr[i + 1];
    int myh = lane >> 3;
    int c0 = 4 * lane;

    float den = 0.f, denb = 0.f;
    float a0 = 0.f, a1 = 0.f, a2 = 0.f, a3 = 0.f;
    float b0 = 0.f, b1 = 0.f, b2 = 0.f, b3 = 0.f;
    int j = start;
    for (; j + 2 <= end; j += 2) {
        float w0 = __expf(g_a1p[j * HEADS + myh]);
        float w1 = __expf(g_a1p[(j + 1) * HEADS + myh]);
        int s0 = g_sde[j].x;
        int s1 = g_sde[j + 1].x;
        float4 x0 = *(const float4*)&g_xl1[s0 * HCD + c0];
        float4 x1 = *(const float4*)&g_xl1[s1 * HCD + c0];
        den += w0; denb += w1;
        a0 = fmaf(w0, x0.x, a0); b0 = fmaf(w1, x1.x, b0);
        a1 = fmaf(w0, x0.y, a1); b1 = fmaf(w1, x1.y, b1);
        a2 = fmaf(w0, x0.z, a2); b2 = fmaf(w1, x1.z, b2);
        a3 = fmaf(w0, x0.w, a3); b3 = fmaf(w1, x1.w, b3);
    }
    if (j < end) {
        float w0 = __expf(g_a1p[j * HEADS + myh]);
        int s0 = g_sde[j].x;
        float4 x0 = *(const float4*)&g_xl1[s0 * HCD + c0];
        den += w0;
        a0 = fmaf(w0, x0.x, a0);
        a1 = fmaf(w0, x0.y, a1);
        a2 = fmaf(w0, x0.z, a2);
        a3 = fmaf(w0, x0.w, a3);
    }
    a0 += b0; a1 += b1; a2 += b2; a3 += b3;
    den += denb;
    float inv = 1.f / (den + 1e-16f);
    float4 bv = *(const float4*)&bias[c0];
    float o0 = a0 * inv + bv.x;
    float o1 = a1 * inv + bv.y;
    float o2 = a2 * inv + bv.z;
    float o3 = a3 * inv + bv.w;
    o0 = o0 > 0.f ? o0 : expm1f(o0);
    o1 = o1 > 0.f ? o1 : expm1f(o1);
    o2 = o2 > 0.f ? o2 : expm1f(o2);
    o3 = o3 > 0.f ? o3 : expm1f(o3);
    *(float4*)&g_h[i * HCD + c0] = make_float4(o0, o1, o2, o3);
}

// ---------------- layer-2 softmax (no max-sub) + aggregate + bias ---------------
__global__ void aggregate2_kernel(const float* __restrict__ bias, float* __restrict__ out) {
    int i = (blockIdx.x * blockDim.x + threadIdx.x) >> 5;
    int lane = threadIdx.x & 31;
    if (i >= NN) return;
    int start = g_rowptr[i], end = g_rowptr[i + 1];
    int c0 = 2 * lane;

    float den = 0.f, denb = 0.f;
    float a0 = 0.f, a1 = 0.f, b0 = 0.f, b1 = 0.f;
    int j = start;
    for (; j + 2 <= end; j += 2) {
        float w0 = __expf(g_a2p[j]);
        float w1 = __expf(g_a2p[j + 1]);
        int s0 = g_sde[j].x;
        int s1 = g_sde[j + 1].x;
        float2 x0 = *(const float2*)&g_xl2[s0 * OUTC + c0];
        float2 x1 = *(const float2*)&g_xl2[s1 * OUTC + c0];
        den += w0; denb += w1;
        a0 = fmaf(w0, x0.x, a0); b0 = fmaf(w1, x1.x, b0);
        a1 = fmaf(w0, x0.y, a1); b1 = fmaf(w1, x1.y, b1);
    }
    if (j < end) {
        float w0 = __expf(g_a2p[j]);
        int s0 = g_sde[j].x;
        float2 x0 = *(const float2*)&g_xl2[s0 * OUTC + c0];
        den += w0;
        a0 = fmaf(w0, x0.x, a0);
        a1 = fmaf(w0, x0.y, a1);
    }
    a0 += b0; a1 += b1; den += denb;
    float inv = 1.f / (den + 1e-16f);
    float o0 = a0 * inv + bias[c0];
    float o1 = a1 * inv + bias[c0 + 1];
    *(float2*)&out[i * OUTC + c0] = make_float2(o0, o1);
}

// ---------------- host launcher ---------------------------------------------------
extern "C" void kernel_launch(void* const* d_in, const int* in_sizes, int n_in,
                              void* d_out, int out_size) {
    const float* x    = (const float*)d_in[0];
    const int*   ei   = (const int*)  d_in[1];
    const float* ea   = (const float*)d_in[2];
    const float* Wl1  = (const float*)d_in[3];
    const float* bl1  = (const float*)d_in[4];
    const float* Wr1  = (const float*)d_in[5];
    const float* br1  = (const float*)d_in[6];
    const float* We1  = (const float*)d_in[7];
    const float* att1 = (const float*)d_in[8];
    const float* bias1= (const float*)d_in[9];
    const float* Wl2  = (const float*)d_in[10];
    const float* bl2  = (const float*)d_in[11];
    const float* Wr2  = (const float*)d_in[12];
    const float* br2  = (const float*)d_in[13];
    const float* We2  = (const float*)d_in[14];
    const float* att2 = (const float*)d_in[15];
    const float* bias2= (const float*)d_in[16];

    const int* src = ei;
    const int* dst = ei + EE;

    void *p_xl1, *p_xr1, *p_h, *p_xl2, *p_xr2, *p_deg, *p_W1p, *p_W2p;
    cudaGetSymbolAddress(&p_xl1, g_xl1);
    cudaGetSymbolAddress(&p_xr1, g_xr1);
    cudaGetSymbolAddress(&p_h,   g_h);
    cudaGetSymbolAddress(&p_xl2, g_xl2);
    cudaGetSymbolAddress(&p_xr2, g_xr2);
    cudaGetSymbolAddress(&p_deg, g_deg);
    cudaGetSymbolAddress(&p_W1p, g_W1p);
    cudaGetSymbolAddress(&p_W2p, g_W2p);

    // weight pre-pack + CSR
    cudaMemsetAsync(p_deg, 0, NN * sizeof(int));
    prepack_kernel<<<108, 256>>>(Wl1, Wr1, Wl2, Wr2, We1, We2);
    csr_count_kernel<<<(EE / 4 + 255) / 256, 256>>>(dst);
    scan_kernel<<<1, 1024>>>();
    csr_fill_kernel<<<(EE + 255) / 256, 256>>>(src, dst);

    // layer 1
    transform_direct<HCD, 256><<<dim3((NN + 127) / 128, 2), 256>>>(
        x, (const uint2*)p_W1p, bl1, br1, (float*)p_xl1, (float*)p_xr1);
    edge_logits1_direct<<<EE / 128, 256>>>(ea, att1);
    aggregate1_kernel<<<NN / 8, 256>>>(bias1);

    // layer 2
    transform_direct<OUTC, 128><<<dim3((NN + 127) / 128, 1), 256>>>(
        (const float*)p_h, (const uint2*)p_W2p, bl2, br2, (float*)p_xl2, (float*)p_xr2);
    edge_logits2_direct<<<EE / 128, 256>>>(ea, att2);
    aggregate2_kernel<<<NN / 8, 256>>>(bias2, (float*)d_out);
}

// round 8
// speedup vs baseline: 1.3228x; 1.0053x over previous
#include <cuda_runtime.h>
#include <math.h>

#define NN 50000
#define EE 800000
#define HCD 128
#define HEADS 4
#define OUTC 64
#define ED 32
#define NEG 0.2f

// ---------------- scratch (device globals) ------------------------------------
__device__ float g_xl1[NN * HCD];
__device__ float g_xr1[NN * HCD];
__device__ float g_h  [NN * HCD];
__device__ float g_xl2[NN * OUTC];
__device__ float g_xr2[NN * OUTC];
__device__ float g_a1p[EE * HEADS];   // exp(logit), CSR slot order, [slot][head]
__device__ float g_a2p[EE];           // exp(logit), CSR slot order
__device__ int   g_deg[NN];
__device__ int   g_rowptr[NN + 1];
__device__ int   g_cursor[NN];
__device__ int4  g_sde[EE];           // CSR slot -> {src, dst, edge, 0}
// pre-packed tf32 B-fragments: [kt][ntg][lane]{b0,b1}
__device__ uint2 g_W1p[16 * 32 * 32];
__device__ uint2 g_W2p[16 * 16 * 32];
__device__ uint2 g_We1p[4 * 16 * 32];
__device__ uint2 g_We2p[4 * 8 * 32];

// ---------------- helpers -------------------------------------------------------
__device__ __forceinline__ unsigned tf32_of(float f) {
    unsigned r;
    asm("cvt.rna.tf32.f32 %0, %1;" : "=r"(r) : "f"(f));
    return r;
}
__device__ __forceinline__ void mma_tf32(float* d,
                                         unsigned a0, unsigned a1, unsigned a2, unsigned a3,
                                         unsigned b0, unsigned b1) {
    asm volatile(
        "mma.sync.aligned.m16n8k8.row.col.f32.tf32.tf32.f32 "
        "{%0,%1,%2,%3}, {%4,%5,%6,%7}, {%8,%9}, {%0,%1,%2,%3};"
        : "+f"(d[0]), "+f"(d[1]), "+f"(d[2]), "+f"(d[3])
        : "r"(a0), "r"(a1), "r"(a2), "r"(a3), "r"(b0), "r"(b1));
}
__device__ __forceinline__ float lrelu(float x) { return x > 0.f ? x : NEG * x; }

// ---------------- weight fragment pre-pack --------------------------------------
__global__ void prepack_kernel(const float* __restrict__ Wl1, const float* __restrict__ Wr1,
                               const float* __restrict__ Wl2, const float* __restrict__ Wr2,
                               const float* __restrict__ We1, const float* __restrict__ We2) {
    int gw = blockIdx.x * 8 + (threadIdx.x >> 5);
    int lane = threadIdx.x & 31, g = lane >> 2, t4 = lane & 3;
    if (gw < 512) {
        int kt = gw >> 5, ntg = gw & 31;
        int c = ntg * 8 + g, k0 = kt * 8 + t4;
        float v0 = (c < 128) ? Wl1[k0 * 128 + c] : Wr1[k0 * 128 + c - 128];
        float v1 = (c < 128) ? Wl1[(k0 + 4) * 128 + c] : Wr1[(k0 + 4) * 128 + c - 128];
        g_W1p[(kt * 32 + ntg) * 32 + lane] = make_uint2(tf32_of(v0), tf32_of(v1));
    } else if (gw < 768) {
        int r = gw - 512;
        int kt = r >> 4, ntg = r & 15;
        int c = ntg * 8 + g, k0 = kt * 8 + t4;
        float v0 = (c < 64) ? Wl2[k0 * 64 + c] : Wr2[k0 * 64 + c - 64];
        float v1 = (c < 64) ? Wl2[(k0 + 4) * 64 + c] : Wr2[(k0 + 4) * 64 + c - 64];
        g_W2p[(kt * 16 + ntg) * 32 + lane] = make_uint2(tf32_of(v0), tf32_of(v1));
    } else if (gw < 832) {
        int r = gw - 768;
        int kt = r >> 4, ntg = r & 15;
        int c = ntg * 8 + g, k0 = kt * 8 + t4;
        g_We1p[(kt * 16 + ntg) * 32 + lane] =
            make_uint2(tf32_of(We1[k0 * 128 + c]), tf32_of(We1[(k0 + 4) * 128 + c]));
    } else if (gw < 864) {
        int r = gw - 832;
        int kt = r >> 3, ntg = r & 7;
        int c = ntg * 8 + g, k0 = kt * 8 + t4;
        g_We2p[(kt * 8 + ntg) * 32 + lane] =
            make_uint2(tf32_of(We2[k0 * 64 + c]), tf32_of(We2[(k0 + 4) * 64 + c]));
    }
}

// ---------------- CSR build -----------------------------------------------------
__global__ void csr_count_kernel(const int* __restrict__ dst) {
    int t = blockIdx.x * blockDim.x + threadIdx.x;
    int e4 = t * 4;
    if (e4 < EE) {
        int4 d = *(const int4*)&dst[e4];
        atomicAdd(&g_deg[d.x], 1);
        atomicAdd(&g_deg[d.y], 1);
        atomicAdd(&g_deg[d.z], 1);
        atomicAdd(&g_deg[d.w], 1);
    }
}

__global__ void scan_kernel() {
    __shared__ int wtot[32];
    __shared__ int carry_sm;
    int t = threadIdx.x, lane = t & 31, wid = t >> 5;
    if (t == 0) carry_sm = 0;
    __syncthreads();
    for (int base = 0; base < NN; base += 4096) {
        int carry = carry_sm;
        int idx = base + t * 4;
        int4 v = make_int4(0, 0, 0, 0);
        if (idx + 3 < NN) v = *(const int4*)&g_deg[idx];
        else {
            if (idx     < NN) v.x = g_deg[idx];
            if (idx + 1 < NN) v.y = g_deg[idx + 1];
            if (idx + 2 < NN) v.z = g_deg[idx + 2];
        }
        int s1 = v.x + v.y, s2 = s1 + v.z, tsum = s2 + v.w;
        int sc = tsum;
        #pragma unroll
        for (int off = 1; off < 32; off <<= 1) {
            int u = __shfl_up_sync(0xffffffffu, sc, off);
            if (lane >= off) sc += u;
        }
        if (lane == 31) wtot[wid] = sc;
        __syncthreads();
        if (wid == 0) {
            int wv = wtot[lane];
            int ws = wv;
            #pragma unroll
            for (int off = 1; off < 32; off <<= 1) {
                int u = __shfl_up_sync(0xffffffffu, ws, off);
                if (lane >= off) ws += u;
            }
            wtot[lane] = ws - wv;
        }
        __syncthreads();
        int off0 = carry + wtot[wid] + (sc - tsum);
        if (idx     < NN) { g_rowptr[idx]     = off0;        g_cursor[idx]     = off0; }
        if (idx + 1 < NN) { int o = off0 + v.x; g_rowptr[idx + 1] = o; g_cursor[idx + 1] = o; }
        if (idx + 2 < NN) { int o = off0 + s1;  g_rowptr[idx + 2] = o; g_cursor[idx + 2] = o; }
        if (idx + 3 < NN) { int o = off0 + s2;  g_rowptr[idx + 3] = o; g_cursor[idx + 3] = o; }
        if (t == 1023) carry_sm = carry + wtot[31] + sc;
        __syncthreads();
    }
    if (t == 0) g_rowptr[NN] = EE;
}

__global__ void csr_fill_kernel(const int* __restrict__ src, const int* __restrict__ dst) {
    int e = blockIdx.x * blockDim.x + threadIdx.x;
    if (e < EE) {
        int d = dst[e];
        int pos = atomicAdd(&g_cursor[d], 1);
        g_sde[pos] = make_int4(src[e], d, e, 0);
    }
}

// ---------------- node transform: smem-staged A + direct-LDG B tf32 MMA ---------
// Block 256 thr = 8 warps (4m x 2n). Block tile: 128 nodes x 128 cols of [Wl|Wr].
// x tile staged per 64-k chunk in smem (stride 68 -> conflict-free frag loads).
template<int OUTD, int TC>
__global__ __launch_bounds__(256) void transform_staged(
    const float* __restrict__ x, const uint2* __restrict__ Wp,
    const float* __restrict__ bl, const float* __restrict__ br,
    float* __restrict__ xl, float* __restrict__ xr) {
    constexpr int NTT = TC / 8;
    __shared__ unsigned xs[128 * 68];
    int tid = threadIdx.x;
    int w = tid >> 5, lane = tid & 31, g = lane >> 2, t4 = lane & 3;
    int mrow = w & 3, ncol = w >> 2;
    int node0 = blockIdx.x * 128;
    int rbase = mrow * 32;
    int ntbase = blockIdx.y * 16 + ncol * 8;

    float acc[2][8][4];
    #pragma unroll
    for (int mt = 0; mt < 2; mt++)
        #pragma unroll
        for (int nt = 0; nt < 8; nt++)
            #pragma unroll
            for (int i = 0; i < 4; i++) acc[mt][nt][i] = 0.f;

    #pragma unroll
    for (int ch = 0; ch < 2; ch++) {
        // stage 128 rows x 64 k (float4 granules: 16 per row)
        __syncthreads();
        for (int idx = tid; idx < 128 * 16; idx += 256) {
            int r = idx >> 4, q = idx & 15;
            int row = node0 + r;
            float4 v = make_float4(0.f, 0.f, 0.f, 0.f);
            if (row < NN) v = *(const float4*)&x[row * 128 + ch * 64 + q * 4];
            unsigned* p = &xs[r * 68 + q * 4];
            p[0] = tf32_of(v.x); p[1] = tf32_of(v.y);
            p[2] = tf32_of(v.z); p[3] = tf32_of(v.w);
        }
        __syncthreads();
        #pragma unroll
        for (int ktl = 0; ktl < 8; ktl++) {
            int kt = ch * 8 + ktl;
            unsigned a[2][4];
            #pragma unroll
            for (int mt = 0; mt < 2; mt++) {
                int r0 = (rbase + mt * 16 + g) * 68 + ktl * 8 + t4;
                a[mt][0] = xs[r0];
                a[mt][1] = xs[r0 + 8 * 68];
                a[mt][2] = xs[r0 + 4];
                a[mt][3] = xs[r0 + 8 * 68 + 4];
            }
            const uint2* wrow = Wp + (kt * NTT + ntbase) * 32 + lane;
            #pragma unroll
            for (int nt = 0; nt < 8; nt++) {
                uint2 b = __ldg(wrow + nt * 32);
                mma_tf32(acc[0][nt], a[0][0], a[0][1], a[0][2], a[0][3], b.x, b.y);
                mma_tf32(acc[1][nt], a[1][0], a[1][1], a[1][2], a[1][3], b.x, b.y);
            }
        }
    }

    #pragma unroll
    for (int nt = 0; nt < 8; nt++) {
        int c = (ntbase + nt) * 8 + t4 * 2;
        const float* bp; float* op; int cc;
        if (c < OUTD) { cc = c; bp = bl; op = xl; }
        else          { cc = c - OUTD; bp = br; op = xr; }
        float2 bv = *(const float2*)&bp[cc];
        #pragma unroll
        for (int mt = 0; mt < 2; mt++) {
            int n0v = node0 + rbase + mt * 16 + g;
            if (n0v < NN)
                *(float2*)&op[n0v * OUTD + cc] =
                    make_float2(acc[mt][nt][0] + bv.x, acc[mt][nt][1] + bv.y);
            int n1v = n0v + 8;
            if (n1v < NN)
                *(float2*)&op[n1v * OUTD + cc] =
                    make_float2(acc[mt][nt][2] + bv.x, acc[mt][nt][3] + bv.y);
        }
    }
}

// ---------------- layer-1 edge logits: CSR-ordered tf32 MMA ---------------------
__global__ __launch_bounds__(256) void edge_logits1_direct(
    const float* __restrict__ ea, const float* __restrict__ att) {
    int tid = threadIdx.x;
    int w = tid >> 5, lane = tid & 31, g = lane >> 2, t4 = lane & 3;
    int sbase = blockIdx.x * 128 + w * 16;

    int4 sd0 = g_sde[sbase + g];
    int4 sd1 = g_sde[sbase + 8 + g];
    int e0 = sd0.z, e1 = sd1.z;

    float d[16][4];
    #pragma unroll
    for (int nt = 0; nt < 16; nt++)
        #pragma unroll
        for (int i = 0; i < 4; i++) d[nt][i] = 0.f;

    #pragma unroll
    for (int kt = 0; kt < 4; kt++) {
        const float* p0 = ea + e0 * 32 + kt * 8 + t4;
        const float* p1 = ea + e1 * 32 + kt * 8 + t4;
        unsigned a0 = tf32_of(__ldg(p0));
        unsigned a1 = tf32_of(__ldg(p1));
        unsigned a2 = tf32_of(__ldg(p0 + 4));
        unsigned a3 = tf32_of(__ldg(p1 + 4));
        const uint2* wrow = g_We1p + (kt * 16) * 32 + lane;
        #pragma unroll
        for (int nt = 0; nt < 16; nt++) {
            uint2 b = __ldg(wrow + nt * 32);
            mma_tf32(d[nt], a0, a1, a2, a3, b.x, b.y);
        }
    }

    const float* xl0 = g_xl1 + sd0.x * HCD;
    const float* xr0 = g_xr1 + sd0.y * HCD;
    const float* xl1r = g_xl1 + sd1.x * HCD;
    const float* xr1r = g_xr1 + sd1.y * HCD;
    float p0h[4] = {0.f, 0.f, 0.f, 0.f};
    float p1h[4] = {0.f, 0.f, 0.f, 0.f};
    #pragma unroll
    for (int nt = 0; nt < 16; nt++) {
        int c = nt * 8 + t4 * 2;
        float2 atv = *(const float2*)&att[c];
        float2 xa = *(const float2*)&xl0[c];
        float2 xb = *(const float2*)&xr0[c];
        float v0 = d[nt][0] + xa.x + xb.x;
        float v1 = d[nt][1] + xa.y + xb.y;
        p0h[nt >> 2] += lrelu(v0) * atv.x + lrelu(v1) * atv.y;
        float2 xc = *(const float2*)&xl1r[c];
        float2 xd = *(const float2*)&xr1r[c];
        float u0 = d[nt][2] + xc.x + xd.x;
        float u1 = d[nt][3] + xc.y + xd.y;
        p1h[nt >> 2] += lrelu(u0) * atv.x + lrelu(u1) * atv.y;
    }
    #pragma unroll
    for (int h = 0; h < 4; h++) {
        p0h[h] += __shfl_xor_sync(0xffffffffu, p0h[h], 1);
        p0h[h] += __shfl_xor_sync(0xffffffffu, p0h[h], 2);
        p1h[h] += __shfl_xor_sync(0xffffffffu, p1h[h], 1);
        p1h[h] += __shfl_xor_sync(0xffffffffu, p1h[h], 2);
    }
    float v0 = (t4 == 0) ? p0h[0] : (t4 == 1) ? p0h[1] : (t4 == 2) ? p0h[2] : p0h[3];
    float v1 = (t4 == 0) ? p1h[0] : (t4 == 1) ? p1h[1] : (t4 == 2) ? p1h[2] : p1h[3];
    g_a1p[(sbase + g) * HEADS + t4]     = __expf(v0);
    g_a1p[(sbase + 8 + g) * HEADS + t4] = __expf(v1);
}

// ---------------- layer-2 edge logits: CSR-ordered tf32 MMA ---------------------
__global__ __launch_bounds__(256) void edge_logits2_direct(
    const float* __restrict__ ea, const float* __restrict__ att) {
    int tid = threadIdx.x;
    int w = tid >> 5, lane = tid & 31, g = lane >> 2, t4 = lane & 3;
    int sbase = blockIdx.x * 128 + w * 16;

    int4 sd0 = g_sde[sbase + g];
    int4 sd1 = g_sde[sbase + 8 + g];
    int e0 = sd0.z, e1 = sd1.z;

    float d[8][4];
    #pragma unroll
    for (int nt = 0; nt < 8; nt++)
        #pragma unroll
        for (int i = 0; i < 4; i++) d[nt][i] = 0.f;

    #pragma unroll
    for (int kt = 0; kt < 4; kt++) {
        const float* p0 = ea + e0 * 32 + kt * 8 + t4;
        const float* p1 = ea + e1 * 32 + kt * 8 + t4;
        unsigned a0 = tf32_of(__ldg(p0));
        unsigned a1 = tf32_of(__ldg(p1));
        unsigned a2 = tf32_of(__ldg(p0 + 4));
        unsigned a3 = tf32_of(__ldg(p1 + 4));
        const uint2* wrow = g_We2p + (kt * 8) * 32 + lane;
        #pragma unroll
        for (int nt = 0; nt < 8; nt++) {
            uint2 b = __ldg(wrow + nt * 32);
            mma_tf32(d[nt], a0, a1, a2, a3, b.x, b.y);
        }
    }

    const float* xl0 = g_xl2 + sd0.x * OUTC;
    const float* xr0 = g_xr2 + sd0.y * OUTC;
    const float* xl1r = g_xl2 + sd1.x * OUTC;
    const float* xr1r = g_xr2 + sd1.y * OUTC;
    float ps0 = 0.f, ps1 = 0.f;
    #pragma unroll
    for (int nt = 0; nt < 8; nt++) {
        int c = nt * 8 + t4 * 2;
        float2 atv = *(const float2*)&att[c];
        float2 xa = *(const float2*)&xl0[c];
        float2 xb = *(const float2*)&xr0[c];
        float v0 = d[nt][0] + xa.x + xb.x;
        float v1 = d[nt][1] + xa.y + xb.y;
        ps0 += lrelu(v0) * atv.x + lrelu(v1) * atv.y;
        float2 xc = *(const float2*)&xl1r[c];
        float2 xd = *(const float2*)&xr1r[c];
        float u0 = d[nt][2] + xc.x + xd.x;
        float u1 = d[nt][3] + xc.y + xd.y;
        ps1 += lrelu(u0) * atv.x + lrelu(u1) * atv.y;
    }
    ps0 += __shfl_xor_sync(0xffffffffu, ps0, 1);
    ps0 += __shfl_xor_sync(0xffffffffu, ps0, 2);
    ps1 += __shfl_xor_sync(0xffffffffu, ps1, 1);
    ps1 += __shfl_xor_sync(0xffffffffu, ps1, 2);
    if (t4 == 0) {
        g_a2p[sbase + g]     = __expf(ps0);
        g_a2p[sbase + 8 + g] = __expf(ps1);
    }
}

// ---------------- layer-1 aggregate: 2 warps/node, shuffle-broadcast ------------
__global__ void aggregate1_kernel(const float* __restrict__ bias) {
    int wi = (blockIdx.x * blockDim.x + threadIdx.x) >> 5;
    int lane = threadIdx.x & 31;
    int i = wi >> 1, half = wi & 1;
    if (i >= NN) return;
    int start = g_rowptr[i], end = g_rowptr[i + 1];
    int c0 = half * 64 + 2 * lane;
    int hsel = lane >> 4;

    float den = 0.f, a0 = 0.f, a1 = 0.f;
    for (int base = start; base < end; base += 32) {
        int n = end - base; if (n > 32) n = 32;
        float2 wv = make_float2(0.f, 0.f);
        int sv = 0;
        if (lane < n) {
            int slot = base + lane;
            wv = *(const float2*)&g_a1p[slot * HEADS + half * 2];
            sv = g_sde[slot].x;
        }
        for (int k = 0; k < n; k++) {
            float wx = __shfl_sync(0xffffffffu, wv.x, k);
            float wy = __shfl_sync(0xffffffffu, wv.y, k);
            int s = __shfl_sync(0xffffffffu, sv, k);
            float wgt = hsel ? wy : wx;
            float2 xv = *(const float2*)&g_xl1[s * HCD + c0];
            den += wgt;
            a0 = fmaf(wgt, xv.x, a0);
            a1 = fmaf(wgt, xv.y, a1);
        }
    }
    float inv = 1.f / (den + 1e-16f);
    float2 bv = *(const float2*)&bias[c0];
    float o0 = a0 * inv + bv.x;
    float o1 = a1 * inv + bv.y;
    o0 = o0 > 0.f ? o0 : expm1f(o0);
    o1 = o1 > 0.f ? o1 : expm1f(o1);
    *(float2*)&g_h[i * HCD + c0] = make_float2(o0, o1);
}

// ---------------- layer-2 aggregate: 1 warp/node, shuffle-broadcast -------------
__global__ void aggregate2_kernel(const float* __restrict__ bias, float* __restrict__ out) {
    int i = (blockIdx.x * blockDim.x + threadIdx.x) >> 5;
    int lane = threadIdx.x & 31;
    if (i >= NN) return;
    int start = g_rowptr[i], end = g_rowptr[i + 1];
    int c0 = 2 * lane;

    float den = 0.f, a0 = 0.f, a1 = 0.f;
    for (int base = start; base < end; base += 32) {
        int n = end - base; if (n > 32) n = 32;
        float wv = 0.f;
        int sv = 0;
        if (lane < n) {
            int slot = base + lane;
            wv = g_a2p[slot];
            sv = g_sde[slot].x;
        }
        for (int k = 0; k < n; k++) {
            float wgt = __shfl_sync(0xffffffffu, wv, k);
            int s = __shfl_sync(0xffffffffu, sv, k);
            float2 xv = *(const float2*)&g_xl2[s * OUTC + c0];
            den += wgt;
            a0 = fmaf(wgt, xv.x, a0);
            a1 = fmaf(wgt, xv.y, a1);
        }
    }
    float inv = 1.f / (den + 1e-16f);
    float o0 = a0 * inv + bias[c0];
    float o1 = a1 * inv + bias[c0 + 1];
    *(float2*)&out[i * OUTC + c0] = make_float2(o0, o1);
}

// ---------------- host launcher ---------------------------------------------------
extern "C" void kernel_launch(void* const* d_in, const int* in_sizes, int n_in,
                              void* d_out, int out_size) {
    const float* x    = (const float*)d_in[0];
    const int*   ei   = (const int*)  d_in[1];
    const float* ea   = (const float*)d_in[2];
    const float* Wl1  = (const float*)d_in[3];
    const float* bl1  = (const float*)d_in[4];
    const float* Wr1  = (const float*)d_in[5];
    const float* br1  = (const float*)d_in[6];
    const float* We1  = (const float*)d_in[7];
    const float* att1 = (const float*)d_in[8];
    const float* bias1= (const float*)d_in[9];
    const float* Wl2  = (const float*)d_in[10];
    const float* bl2  = (const float*)d_in[11];
    const float* Wr2  = (const float*)d_in[12];
    const float* br2  = (const float*)d_in[13];
    const float* We2  = (const float*)d_in[14];
    const float* att2 = (const float*)d_in[15];
    const float* bias2= (const float*)d_in[16];

    const int* src = ei;
    const int* dst = ei + EE;

    void *p_xl1, *p_xr1, *p_h, *p_xl2, *p_xr2, *p_deg, *p_W1p, *p_W2p;
    cudaGetSymbolAddress(&p_xl1, g_xl1);
    cudaGetSymbolAddress(&p_xr1, g_xr1);
    cudaGetSymbolAddress(&p_h,   g_h);
    cudaGetSymbolAddress(&p_xl2, g_xl2);
    cudaGetSymbolAddress(&p_xr2, g_xr2);
    cudaGetSymbolAddress(&p_deg, g_deg);
    cudaGetSymbolAddress(&p_W1p, g_W1p);
    cudaGetSymbolAddress(&p_W2p, g_W2p);

    // weight pre-pack + CSR
    cudaMemsetAsync(p_deg, 0, NN * sizeof(int));
    prepack_kernel<<<108, 256>>>(Wl1, Wr1, Wl2, Wr2, We1, We2);
    csr_count_kernel<<<(EE / 4 + 255) / 256, 256>>>(dst);
    scan_kernel<<<1, 1024>>>();
    csr_fill_kernel<<<(EE + 255) / 256, 256>>>(src, dst);

    // layer 1
    transform_staged<HCD, 256><<<dim3((NN + 127) / 128, 2), 256>>>(
        x, (const uint2*)p_W1p, bl1, br1, (float*)p_xl1, (float*)p_xr1);
    edge_logits1_direct<<<EE / 128, 256>>>(ea, att1);
    aggregate1_kernel<<<(2 * NN + 7) / 8, 256>>>(bias1);

    // layer 2
    transform_staged<OUTC, 128><<<dim3((NN + 127) / 128, 1), 256>>>(
        (const float*)p_h, (const uint2*)p_W2p, bl2, br2, (float*)p_xl2, (float*)p_xr2);
    edge_logits2_direct<<<EE / 128, 256>>>(ea, att2);
    aggregate2_kernel<<<NN / 8, 256>>>(bias2, (float*)d_out);
}

// round 9
// speedup vs baseline: 1.4297x; 1.0808x over previous
#include <cuda_runtime.h>
#include <math.h>

#define NN 50000
#define EE 800000
#define HCD 128
#define HEADS 4
#define OUTC 64
#define ED 32
#define NEG 0.2f

// ---------------- scratch (device globals) ------------------------------------
__device__ float g_xl1[NN * HCD];
__device__ float g_xr1[NN * HCD];
__device__ float g_h  [NN * HCD];
__device__ float g_xl2[NN * OUTC];
__device__ float g_xr2[NN * OUTC];
__device__ float g_a1p[EE * HEADS];   // exp(logit), CSR slot order, [slot][head]
__device__ float g_a2p[EE];           // exp(logit), CSR slot order
__device__ int   g_deg[NN];
__device__ int   g_rowptr[NN + 1];
__device__ int   g_cursor[NN];
__device__ int4  g_sde[EE];           // CSR slot -> {src, dst, edge, 0}
// pre-packed tf32 B-fragments: [kt][ntg][lane]{b0,b1}
__device__ uint2 g_W1p[16 * 32 * 32];
__device__ uint2 g_W2p[16 * 16 * 32];
__device__ uint2 g_We1p[4 * 16 * 32];
__device__ uint2 g_We2p[4 * 8 * 32];

// ---------------- helpers -------------------------------------------------------
__device__ __forceinline__ unsigned tf32_of(float f) {
    unsigned r;
    asm("cvt.rna.tf32.f32 %0, %1;" : "=r"(r) : "f"(f));
    return r;
}
__device__ __forceinline__ void mma_tf32(float* d,
                                         unsigned a0, unsigned a1, unsigned a2, unsigned a3,
                                         unsigned b0, unsigned b1) {
    asm volatile(
        "mma.sync.aligned.m16n8k8.row.col.f32.tf32.tf32.f32 "
        "{%0,%1,%2,%3}, {%4,%5,%6,%7}, {%8,%9}, {%0,%1,%2,%3};"
        : "+f"(d[0]), "+f"(d[1]), "+f"(d[2]), "+f"(d[3])
        : "r"(a0), "r"(a1), "r"(a2), "r"(a3), "r"(b0), "r"(b1));
}
__device__ __forceinline__ float lrelu(float x) { return x > 0.f ? x : NEG * x; }

// ---------------- weight fragment pre-pack --------------------------------------
__global__ void prepack_kernel(const float* __restrict__ Wl1, const float* __restrict__ Wr1,
                               const float* __restrict__ Wl2, const float* __restrict__ Wr2,
                               const float* __restrict__ We1, const float* __restrict__ We2) {
    int gw = blockIdx.x * 8 + (threadIdx.x >> 5);
    int lane = threadIdx.x & 31, g = lane >> 2, t4 = lane & 3;
    if (gw < 512) {
        int kt = gw >> 5, ntg = gw & 31;
        int c = ntg * 8 + g, k0 = kt * 8 + t4;
        float v0 = (c < 128) ? Wl1[k0 * 128 + c] : Wr1[k0 * 128 + c - 128];
        float v1 = (c < 128) ? Wl1[(k0 + 4) * 128 + c] : Wr1[(k0 + 4) * 128 + c - 128];
        g_W1p[(kt * 32 + ntg) * 32 + lane] = make_uint2(tf32_of(v0), tf32_of(v1));
    } else if (gw < 768) {
        int r = gw - 512;
        int kt = r >> 4, ntg = r & 15;
        int c = ntg * 8 + g, k0 = kt * 8 + t4;
        float v0 = (c < 64) ? Wl2[k0 * 64 + c] : Wr2[k0 * 64 + c - 64];
        float v1 = (c < 64) ? Wl2[(k0 + 4) * 64 + c] : Wr2[(k0 + 4) * 64 + c - 64];
        g_W2p[(kt * 16 + ntg) * 32 + lane] = make_uint2(tf32_of(v0), tf32_of(v1));
    } else if (gw < 832) {
        int r = gw - 768;
        int kt = r >> 4, ntg = r & 15;
        int c = ntg * 8 + g, k0 = kt * 8 + t4;
        g_We1p[(kt * 16 + ntg) * 32 + lane] =
            make_uint2(tf32_of(We1[k0 * 128 + c]), tf32_of(We1[(k0 + 4) * 128 + c]));
    } else if (gw < 864) {
        int r = gw - 832;
        int kt = r >> 3, ntg = r & 7;
        int c = ntg * 8 + g, k0 = kt * 8 + t4;
        g_We2p[(kt * 8 + ntg) * 32 + lane] =
            make_uint2(tf32_of(We2[k0 * 64 + c]), tf32_of(We2[(k0 + 4) * 64 + c]));
    }
}

// ---------------- CSR build -----------------------------------------------------
__global__ void csr_count_kernel(const int* __restrict__ dst) {
    int t = blockIdx.x * blockDim.x + threadIdx.x;
    int e4 = t * 4;
    if (e4 < EE) {
        int4 d = *(const int4*)&dst[e4];
        atomicAdd(&g_deg[d.x], 1);
        atomicAdd(&g_deg[d.y], 1);
        atomicAdd(&g_deg[d.z], 1);
        atomicAdd(&g_deg[d.w], 1);
    }
}

__global__ void scan_kernel() {
    __shared__ int wtot[32];
    __shared__ int carry_sm;
    int t = threadIdx.x, lane = t & 31, wid = t >> 5;
    if (t == 0) carry_sm = 0;
    __syncthreads();
    for (int base = 0; base < NN; base += 4096) {
        int carry = carry_sm;
        int idx = base + t * 4;
        int4 v = make_int4(0, 0, 0, 0);
        if (idx + 3 < NN) v = *(const int4*)&g_deg[idx];
        else {
            if (idx     < NN) v.x = g_deg[idx];
            if (idx + 1 < NN) v.y = g_deg[idx + 1];
            if (idx + 2 < NN) v.z = g_deg[idx + 2];
        }
        int s1 = v.x + v.y, s2 = s1 + v.z, tsum = s2 + v.w;
        int sc = tsum;
        #pragma unroll
        for (int off = 1; off < 32; off <<= 1) {
            int u = __shfl_up_sync(0xffffffffu, sc, off);
            if (lane >= off) sc += u;
        }
        if (lane == 31) wtot[wid] = sc;
        __syncthreads();
        if (wid == 0) {
            int wv = wtot[lane];
            int ws = wv;
            #pragma unroll
            for (int off = 1; off < 32; off <<= 1) {
                int u = __shfl_up_sync(0xffffffffu, ws, off);
                if (lane >= off) ws += u;
            }
            wtot[lane] = ws - wv;
        }
        __syncthreads();
        int off0 = carry + wtot[wid] + (sc - tsum);
        if (idx     < NN) { g_rowptr[idx]     = off0;        g_cursor[idx]     = off0; }
        if (idx + 1 < NN) { int o = off0 + v.x; g_rowptr[idx + 1] = o; g_cursor[idx + 1] = o; }
        if (idx + 2 < NN) { int o = off0 + s1;  g_rowptr[idx + 2] = o; g_cursor[idx + 2] = o; }
        if (idx + 3 < NN) { int o = off0 + s2;  g_rowptr[idx + 3] = o; g_cursor[idx + 3] = o; }
        if (t == 1023) carry_sm = carry + wtot[31] + sc;
        __syncthreads();
    }
    if (t == 0) g_rowptr[NN] = EE;
}

__global__ void csr_fill_kernel(const int* __restrict__ src, const int* __restrict__ dst) {
    int e = blockIdx.x * blockDim.x + threadIdx.x;
    if (e < EE) {
        int d = dst[e];
        int pos = atomicAdd(&g_cursor[d], 1);
        g_sde[pos] = make_int4(src[e], d, e, 0);
    }
}

// ---------------- node transform: smem-staged A + direct-LDG B tf32 MMA ---------
template<int OUTD, int TC>
__global__ __launch_bounds__(256) void transform_staged(
    const float* __restrict__ x, const uint2* __restrict__ Wp,
    const float* __restrict__ bl, const float* __restrict__ br,
    float* __restrict__ xl, float* __restrict__ xr) {
    constexpr int NTT = TC / 8;
    __shared__ unsigned xs[128 * 68];
    int tid = threadIdx.x;
    int w = tid >> 5, lane = tid & 31, g = lane >> 2, t4 = lane & 3;
    int mrow = w & 3, ncol = w >> 2;
    int node0 = blockIdx.x * 128;
    int rbase = mrow * 32;
    int ntbase = blockIdx.y * 16 + ncol * 8;

    float acc[2][8][4];
    #pragma unroll
    for (int mt = 0; mt < 2; mt++)
        #pragma unroll
        for (int nt = 0; nt < 8; nt++)
            #pragma unroll
            for (int i = 0; i < 4; i++) acc[mt][nt][i] = 0.f;

    #pragma unroll
    for (int ch = 0; ch < 2; ch++) {
        __syncthreads();
        for (int idx = tid; idx < 128 * 16; idx += 256) {
            int r = idx >> 4, q = idx & 15;
            int row = node0 + r;
            float4 v = make_float4(0.f, 0.f, 0.f, 0.f);
            if (row < NN) v = *(const float4*)&x[row * 128 + ch * 64 + q * 4];
            unsigned* p = &xs[r * 68 + q * 4];
            p[0] = tf32_of(v.x); p[1] = tf32_of(v.y);
            p[2] = tf32_of(v.z); p[3] = tf32_of(v.w);
        }
        __syncthreads();
        #pragma unroll
        for (int ktl = 0; ktl < 8; ktl++) {
            int kt = ch * 8 + ktl;
            unsigned a[2][4];
            #pragma unroll
            for (int mt = 0; mt < 2; mt++) {
                int r0 = (rbase + mt * 16 + g) * 68 + ktl * 8 + t4;
                a[mt][0] = xs[r0];
                a[mt][1] = xs[r0 + 8 * 68];
                a[mt][2] = xs[r0 + 4];
                a[mt][3] = xs[r0 + 8 * 68 + 4];
            }
            const uint2* wrow = Wp + (kt * NTT + ntbase) * 32 + lane;
            #pragma unroll
            for (int nt = 0; nt < 8; nt++) {
                uint2 b = __ldg(wrow + nt * 32);
                mma_tf32(acc[0][nt], a[0][0], a[0][1], a[0][2], a[0][3], b.x, b.y);
                mma_tf32(acc[1][nt], a[1][0], a[1][1], a[1][2], a[1][3], b.x, b.y);
            }
        }
    }

    #pragma unroll
    for (int nt = 0; nt < 8; nt++) {
        int c = (ntbase + nt) * 8 + t4 * 2;
        const float* bp; float* op; int cc;
        if (c < OUTD) { cc = c; bp = bl; op = xl; }
        else          { cc = c - OUTD; bp = br; op = xr; }
        float2 bv = *(const float2*)&bp[cc];
        #pragma unroll
        for (int mt = 0; mt < 2; mt++) {
            int n0v = node0 + rbase + mt * 16 + g;
            if (n0v < NN)
                *(float2*)&op[n0v * OUTD + cc] =
                    make_float2(acc[mt][nt][0] + bv.x, acc[mt][nt][1] + bv.y);
            int n1v = n0v + 8;
            if (n1v < NN)
                *(float2*)&op[n1v * OUTD + cc] =
                    make_float2(acc[mt][nt][2] + bv.x, acc[mt][nt][3] + bv.y);
        }
    }
}

// ---------------- layer-1 edge logits: CSR-ordered tf32 MMA ---------------------
__global__ __launch_bounds__(256) void edge_logits1_direct(
    const float* __restrict__ ea, const float* __restrict__ att) {
    int tid = threadIdx.x;
    int w = tid >> 5, lane = tid & 31, g = lane >> 2, t4 = lane & 3;
    int sbase = blockIdx.x * 128 + w * 16;

    int4 sd0 = g_sde[sbase + g];
    int4 sd1 = g_sde[sbase + 8 + g];
    int e0 = sd0.z, e1 = sd1.z;

    float d[16][4];
    #pragma unroll
    for (int nt = 0; nt < 16; nt++)
        #pragma unroll
        for (int i = 0; i < 4; i++) d[nt][i] = 0.f;

    #pragma unroll
    for (int kt = 0; kt < 4; kt++) {
        const float* p0 = ea + e0 * 32 + kt * 8 + t4;
        const float* p1 = ea + e1 * 32 + kt * 8 + t4;
        unsigned a0 = tf32_of(__ldg(p0));
        unsigned a1 = tf32_of(__ldg(p1));
        unsigned a2 = tf32_of(__ldg(p0 + 4));
        unsigned a3 = tf32_of(__ldg(p1 + 4));
        const uint2* wrow = g_We1p + (kt * 16) * 32 + lane;
        #pragma unroll
        for (int nt = 0; nt < 16; nt++) {
            uint2 b = __ldg(wrow + nt * 32);
            mma_tf32(d[nt], a0, a1, a2, a3, b.x, b.y);
        }
    }

    const float* xl0 = g_xl1 + sd0.x * HCD;
    const float* xr0 = g_xr1 + sd0.y * HCD;
    const float* xl1r = g_xl1 + sd1.x * HCD;
    const float* xr1r = g_xr1 + sd1.y * HCD;
    float p0h[4] = {0.f, 0.f, 0.f, 0.f};
    float p1h[4] = {0.f, 0.f, 0.f, 0.f};
    #pragma unroll
    for (int nt = 0; nt < 16; nt++) {
        int c = nt * 8 + t4 * 2;
        float2 atv = *(const float2*)&att[c];
        float2 xa = *(const float2*)&xl0[c];
        float2 xb = *(const float2*)&xr0[c];
        float v0 = d[nt][0] + xa.x + xb.x;
        float v1 = d[nt][1] + xa.y + xb.y;
        p0h[nt >> 2] += lrelu(v0) * atv.x + lrelu(v1) * atv.y;
        float2 xc = *(const float2*)&xl1r[c];
        float2 xd = *(const float2*)&xr1r[c];
        float u0 = d[nt][2] + xc.x + xd.x;
        float u1 = d[nt][3] + xc.y + xd.y;
        p1h[nt >> 2] += lrelu(u0) * atv.x + lrelu(u1) * atv.y;
    }
    #pragma unroll
    for (int h = 0; h < 4; h++) {
        p0h[h] += __shfl_xor_sync(0xffffffffu, p0h[h], 1);
        p0h[h] += __shfl_xor_sync(0xffffffffu, p0h[h], 2);
        p1h[h] += __shfl_xor_sync(0xffffffffu, p1h[h], 1);
        p1h[h] += __shfl_xor_sync(0xffffffffu, p1h[h], 2);
    }
    float v0 = (t4 == 0) ? p0h[0] : (t4 == 1) ? p0h[1] : (t4 == 2) ? p0h[2] : p0h[3];
    float v1 = (t4 == 0) ? p1h[0] : (t4 == 1) ? p1h[1] : (t4 == 2) ? p1h[2] : p1h[3];
    g_a1p[(sbase + g) * HEADS + t4]     = __expf(v0);
    g_a1p[(sbase + 8 + g) * HEADS + t4] = __expf(v1);
}

// ---------------- layer-2 edge logits: CSR-ordered tf32 MMA ---------------------
__global__ __launch_bounds__(256) void edge_logits2_direct(
    const float* __restrict__ ea, const float* __restrict__ att) {
    int tid = threadIdx.x;
    int w = tid >> 5, lane = tid & 31, g = lane >> 2, t4 = lane & 3;
    int sbase = blockIdx.x * 128 + w * 16;

    int4 sd0 = g_sde[sbase + g];
    int4 sd1 = g_sde[sbase + 8 + g];
    int e0 = sd0.z, e1 = sd1.z;

    float d[8][4];
    #pragma unroll
    for (int nt = 0; nt < 8; nt++)
        #pragma unroll
        for (int i = 0; i < 4; i++) d[nt][i] = 0.f;

    #pragma unroll
    for (int kt = 0; kt < 4; kt++) {
        const float* p0 = ea + e0 * 32 + kt * 8 + t4;
        const float* p1 = ea + e1 * 32 + kt * 8 + t4;
        unsigned a0 = tf32_of(__ldg(p0));
        unsigned a1 = tf32_of(__ldg(p1));
        unsigned a2 = tf32_of(__ldg(p0 + 4));
        unsigned a3 = tf32_of(__ldg(p1 + 4));
        const uint2* wrow = g_We2p + (kt * 8) * 32 + lane;
        #pragma unroll
        for (int nt = 0; nt < 8; nt++) {
            uint2 b = __ldg(wrow + nt * 32);
            mma_tf32(d[nt], a0, a1, a2, a3, b.x, b.y);
        }
    }

    const float* xl0 = g_xl2 + sd0.x * OUTC;
    const float* xr0 = g_xr2 + sd0.y * OUTC;
    const float* xl1r = g_xl2 + sd1.x * OUTC;
    const float* xr1r = g_xr2 + sd1.y * OUTC;
    float ps0 = 0.f, ps1 = 0.f;
    #pragma unroll
    for (int nt = 0; nt < 8; nt++) {
        int c = nt * 8 + t4 * 2;
        float2 atv = *(const float2*)&att[c];
        float2 xa = *(const float2*)&xl0[c];
        float2 xb = *(const float2*)&xr0[c];
        float v0 = d[nt][0] + xa.x + xb.x;
        float v1 = d[nt][1] + xa.y + xb.y;
        ps0 += lrelu(v0) * atv.x + lrelu(v1) * atv.y;
        float2 xc = *(const float2*)&xl1r[c];
        float2 xd = *(const float2*)&xr1r[c];
        float u0 = d[nt][2] + xc.x + xd.x;
        float u1 = d[nt][3] + xc.y + xd.y;
        ps1 += lrelu(u0) * atv.x + lrelu(u1) * atv.y;
    }
    ps0 += __shfl_xor_sync(0xffffffffu, ps0, 1);
    ps0 += __shfl_xor_sync(0xffffffffu, ps0, 2);
    ps1 += __shfl_xor_sync(0xffffffffu, ps1, 1);
    ps1 += __shfl_xor_sync(0xffffffffu, ps1, 2);
    if (t4 == 0) {
        g_a2p[sbase + g]     = __expf(ps0);
        g_a2p[sbase + 8 + g] = __expf(ps1);
    }
}

// ---------------- layer-1 aggregate: 2 warps/node, shuffle-broadcast ------------
__global__ void aggregate1_kernel(const float* __restrict__ bias) {
    int wi = (blockIdx.x * blockDim.x + threadIdx.x) >> 5;
    int lane = threadIdx.x & 31;
    int i = wi >> 1, half = wi & 1;
    if (i >= NN) return;
    int start = g_rowptr[i], end = g_rowptr[i + 1];
    int c0 = half * 64 + 2 * lane;
    int hsel = lane >> 4;

    float den = 0.f, a0 = 0.f, a1 = 0.f;
    for (int base = start; base < end; base += 32) {
        int n = end - base; if (n > 32) n = 32;
        float2 wv = make_float2(0.f, 0.f);
        int sv = 0;
        if (lane < n) {
            int slot = base + lane;
            wv = *(const float2*)&g_a1p[slot * HEADS + half * 2];
            sv = g_sde[slot].x;
        }
        for (int k = 0; k < n; k++) {
            float wx = __shfl_sync(0xffffffffu, wv.x, k);
            float wy = __shfl_sync(0xffffffffu, wv.y, k);
            int s = __shfl_sync(0xffffffffu, sv, k);
            float wgt = hsel ? wy : wx;
            float2 xv = *(const float2*)&g_xl1[s * HCD + c0];
            den += wgt;
            a0 = fmaf(wgt, xv.x, a0);
            a1 = fmaf(wgt, xv.y, a1);
        }
    }
    float inv = 1.f / (den + 1e-16f);
    float2 bv = *(const float2*)&bias[c0];
    float o0 = a0 * inv + bv.x;
    float o1 = a1 * inv + bv.y;
    o0 = o0 > 0.f ? o0 : expm1f(o0);
    o1 = o1 > 0.f ? o1 : expm1f(o1);
    *(float2*)&g_h[i * HCD + c0] = make_float2(o0, o1);
}

// ---------------- layer-2 aggregate: 1 warp/node, shuffle-broadcast -------------
__global__ void aggregate2_kernel(const float* __restrict__ bias, float* __restrict__ out) {
    int i = (blockIdx.x * blockDim.x + threadIdx.x) >> 5;
    int lane = threadIdx.x & 31;
    if (i >= NN) return;
    int start = g_rowptr[i], end = g_rowptr[i + 1];
    int c0 = 2 * lane;

    float den = 0.f, a0 = 0.f, a1 = 0.f;
    for (int base = start; base < end; base += 32) {
        int n = end - base; if (n > 32) n = 32;
        float wv = 0.f;
        int sv = 0;
        if (lane < n) {
            int slot = base + lane;
            wv = g_a2p[slot];
            sv = g_sde[slot].x;
        }
        for (int k = 0; k < n; k++) {
            float wgt = __shfl_sync(0xffffffffu, wv, k);
            int s = __shfl_sync(0xffffffffu, sv, k);
            float2 xv = *(const float2*)&g_xl2[s * OUTC + c0];
            den += wgt;
            a0 = fmaf(wgt, xv.x, a0);
            a1 = fmaf(wgt, xv.y, a1);
        }
    }
    float inv = 1.f / (den + 1e-16f);
    float o0 = a0 * inv + bias[c0];
    float o1 = a1 * inv + bias[c0 + 1];
    *(float2*)&out[i * OUTC + c0] = make_float2(o0, o1);
}

// ---------------- host launcher ---------------------------------------------------
extern "C" void kernel_launch(void* const* d_in, const int* in_sizes, int n_in,
                              void* d_out, int out_size) {
    const float* x    = (const float*)d_in[0];
    const int*   ei   = (const int*)  d_in[1];
    const float* ea   = (const float*)d_in[2];
    const float* Wl1  = (const float*)d_in[3];
    const float* bl1  = (const float*)d_in[4];
    const float* Wr1  = (const float*)d_in[5];
    const float* br1  = (const float*)d_in[6];
    const float* We1  = (const float*)d_in[7];
    const float* att1 = (const float*)d_in[8];
    const float* bias1= (const float*)d_in[9];
    const float* Wl2  = (const float*)d_in[10];
    const float* bl2  = (const float*)d_in[11];
    const float* Wr2  = (const float*)d_in[12];
    const float* br2  = (const float*)d_in[13];
    const float* We2  = (const float*)d_in[14];
    const float* att2 = (const float*)d_in[15];
    const float* bias2= (const float*)d_in[16];

    const int* src = ei;
    const int* dst = ei + EE;

    void *p_xl1, *p_xr1, *p_h, *p_xl2, *p_xr2, *p_deg, *p_W1p, *p_W2p;
    cudaGetSymbolAddress(&p_xl1, g_xl1);
    cudaGetSymbolAddress(&p_xr1, g_xr1);
    cudaGetSymbolAddress(&p_h,   g_h);
    cudaGetSymbolAddress(&p_xl2, g_xl2);
    cudaGetSymbolAddress(&p_xr2, g_xr2);
    cudaGetSymbolAddress(&p_deg, g_deg);
    cudaGetSymbolAddress(&p_W1p, g_W1p);
    cudaGetSymbolAddress(&p_W2p, g_W2p);

    // one-time host-side stream/event objects (no device memory involved)
    static cudaStream_t s_csr = nullptr;
    static cudaEvent_t ev_fork = nullptr, ev_csr_done = nullptr;
    if (s_csr == nullptr) {
        cudaStreamCreateWithFlags(&s_csr, cudaStreamNonBlocking);
        cudaEventCreateWithFlags(&ev_fork, cudaEventDisableTiming);
        cudaEventCreateWithFlags(&ev_csr_done, cudaEventDisableTiming);
    }

    // fork: CSR branch on s_csr, weight-prep + transform1 on main stream
    cudaEventRecord(ev_fork, 0);
    cudaStreamWaitEvent(s_csr, ev_fork, 0);

    // --- CSR branch (side stream) ---
    cudaMemsetAsync(p_deg, 0, NN * sizeof(int), s_csr);
    csr_count_kernel<<<(EE / 4 + 255) / 256, 256, 0, s_csr>>>(dst);
    scan_kernel<<<1, 1024, 0, s_csr>>>();
    csr_fill_kernel<<<(EE + 255) / 256, 256, 0, s_csr>>>(src, dst);
    cudaEventRecord(ev_csr_done, s_csr);

    // --- main branch ---
    prepack_kernel<<<108, 256>>>(Wl1, Wr1, Wl2, Wr2, We1, We2);
    transform_staged<HCD, 256><<<dim3((NN + 127) / 128, 2), 256>>>(
        x, (const uint2*)p_W1p, bl1, br1, (float*)p_xl1, (float*)p_xr1);

    // join: logits1 needs CSR + transform1 + prepack
    cudaStreamWaitEvent(0, ev_csr_done, 0);

    edge_logits1_direct<<<EE / 128, 256>>>(ea, att1);
    aggregate1_kernel<<<(2 * NN + 7) / 8, 256>>>(bias1);

    // layer 2
    transform_staged<OUTC, 128><<<dim3((NN + 127) / 128, 1), 256>>>(
        (const float*)p_h, (const uint2*)p_W2p, bl2, br2, (float*)p_xl2, (float*)p_xr2);
    edge_logits2_direct<<<EE / 128, 256>>>(ea, att2);
    aggregate2_kernel<<<NN / 8, 256>>>(bias2, (float*)d_out);
}

// round 10
// speedup vs baseline: 1.4366x; 1.0048x over previous
#include <cuda_runtime.h>
#include <cuda_fp16.h>
#include <math.h>

#define NN 50000
#define EE 800000
#define HCD 128
#define HEADS 4
#define OUTC 64
#define ED 32
#define NEG 0.2f

// ---------------- scratch (device globals) ------------------------------------
__device__ __half g_xl1h[NN * HCD];   // fp16 source-transform (gathered twice/edge)
__device__ float  g_xr1[NN * HCD];
__device__ float  g_h  [NN * HCD];
__device__ __half g_xl2h[NN * OUTC];
__device__ float  g_xr2[NN * OUTC];
__device__ float  g_a1p[EE * HEADS];  // exp(logit), CSR slot order, [slot][head]
__device__ float  g_a2p[EE];          // exp(logit), CSR slot order
__device__ int    g_deg[NN];
__device__ int    g_rowptr[NN + 1];
__device__ int    g_cursor[NN];
__device__ int4   g_sde[EE];          // CSR slot -> {src, dst, edge, 0}
// pre-packed tf32 B-fragments: [kt][ntg][lane]{b0,b1}
__device__ uint2 g_W1p[16 * 32 * 32];
__device__ uint2 g_W2p[16 * 16 * 32];
__device__ uint2 g_We1p[4 * 16 * 32];
__device__ uint2 g_We2p[4 * 8 * 32];

// ---------------- helpers -------------------------------------------------------
__device__ __forceinline__ unsigned tf32_of(float f) {
    unsigned r;
    asm("cvt.rna.tf32.f32 %0, %1;" : "=r"(r) : "f"(f));
    return r;
}
__device__ __forceinline__ void mma_tf32(float* d,
                                         unsigned a0, unsigned a1, unsigned a2, unsigned a3,
                                         unsigned b0, unsigned b1) {
    asm volatile(
        "mma.sync.aligned.m16n8k8.row.col.f32.tf32.tf32.f32 "
        "{%0,%1,%2,%3}, {%4,%5,%6,%7}, {%8,%9}, {%0,%1,%2,%3};"
        : "+f"(d[0]), "+f"(d[1]), "+f"(d[2]), "+f"(d[3])
        : "r"(a0), "r"(a1), "r"(a2), "r"(a3), "r"(b0), "r"(b1));
}
__device__ __forceinline__ float lrelu(float x) { return x > 0.f ? x : NEG * x; }

// ---------------- weight fragment pre-pack --------------------------------------
__global__ void prepack_kernel(const float* __restrict__ Wl1, const float* __restrict__ Wr1,
                               const float* __restrict__ Wl2, const float* __restrict__ Wr2,
                               const float* __restrict__ We1, const float* __restrict__ We2) {
    int gw = blockIdx.x * 8 + (threadIdx.x >> 5);
    int lane = threadIdx.x & 31, g = lane >> 2, t4 = lane & 3;
    if (gw < 512) {
        int kt = gw >> 5, ntg = gw & 31;
        int c = ntg * 8 + g, k0 = kt * 8 + t4;
        float v0 = (c < 128) ? Wl1[k0 * 128 + c] : Wr1[k0 * 128 + c - 128];
        float v1 = (c < 128) ? Wl1[(k0 + 4) * 128 + c] : Wr1[(k0 + 4) * 128 + c - 128];
        g_W1p[(kt * 32 + ntg) * 32 + lane] = make_uint2(tf32_of(v0), tf32_of(v1));
    } else if (gw < 768) {
        int r = gw - 512;
        int kt = r >> 4, ntg = r & 15;
        int c = ntg * 8 + g, k0 = kt * 8 + t4;
        float v0 = (c < 64) ? Wl2[k0 * 64 + c] : Wr2[k0 * 64 + c - 64];
        float v1 = (c < 64) ? Wl2[(k0 + 4) * 64 + c] : Wr2[(k0 + 4) * 64 + c - 64];
        g_W2p[(kt * 16 + ntg) * 32 + lane] = make_uint2(tf32_of(v0), tf32_of(v1));
    } else if (gw < 832) {
        int r = gw - 768;
        int kt = r >> 4, ntg = r & 15;
        int c = ntg * 8 + g, k0 = kt * 8 + t4;
        g_We1p[(kt * 16 + ntg) * 32 + lane] =
            make_uint2(tf32_of(We1[k0 * 128 + c]), tf32_of(We1[(k0 + 4) * 128 + c]));
    } else if (gw < 864) {
        int r = gw - 832;
        int kt = r >> 3, ntg = r & 7;
        int c = ntg * 8 + g, k0 = kt * 8 + t4;
        g_We2p[(kt * 8 + ntg) * 32 + lane] =
            make_uint2(tf32_of(We2[k0 * 64 + c]), tf32_of(We2[(k0 + 4) * 64 + c]));
    }
}

// ---------------- CSR build -----------------------------------------------------
__global__ void csr_count_kernel(const int* __restrict__ dst) {
    int t = blockIdx.x * blockDim.x + threadIdx.x;
    int e4 = t * 4;
    if (e4 < EE) {
        int4 d = *(const int4*)&dst[e4];
        atomicAdd(&g_deg[d.x], 1);
        atomicAdd(&g_deg[d.y], 1);
        atomicAdd(&g_deg[d.z], 1);
        atomicAdd(&g_deg[d.w], 1);
    }
}

__global__ void scan_kernel() {
    __shared__ int wtot[32];
    __shared__ int carry_sm;
    int t = threadIdx.x, lane = t & 31, wid = t >> 5;
    if (t == 0) carry_sm = 0;
    __syncthreads();
    for (int base = 0; base < NN; base += 4096) {
        int carry = carry_sm;
        int idx = base + t * 4;
        int4 v = make_int4(0, 0, 0, 0);
        if (idx + 3 < NN) v = *(const int4*)&g_deg[idx];
        else {
            if (idx     < NN) v.x = g_deg[idx];
            if (idx + 1 < NN) v.y = g_deg[idx + 1];
            if (idx + 2 < NN) v.z = g_deg[idx + 2];
        }
        int s1 = v.x + v.y, s2 = s1 + v.z, tsum = s2 + v.w;
        int sc = tsum;
        #pragma unroll
        for (int off = 1; off < 32; off <<= 1) {
            int u = __shfl_up_sync(0xffffffffu, sc, off);
            if (lane >= off) sc += u;
        }
        if (lane == 31) wtot[wid] = sc;
        __syncthreads();
        if (wid == 0) {
            int wv = wtot[lane];
            int ws = wv;
            #pragma unroll
            for (int off = 1; off < 32; off <<= 1) {
                int u = __shfl_up_sync(0xffffffffu, ws, off);
                if (lane >= off) ws += u;
            }
            wtot[lane] = ws - wv;
        }
        __syncthreads();
        int off0 = carry + wtot[wid] + (sc - tsum);
        if (idx     < NN) { g_rowptr[idx]     = off0;        g_cursor[idx]     = off0; }
        if (idx + 1 < NN) { int o = off0 + v.x; g_rowptr[idx + 1] = o; g_cursor[idx + 1] = o; }
        if (idx + 2 < NN) { int o = off0 + s1;  g_rowptr[idx + 2] = o; g_cursor[idx + 2] = o; }
        if (idx + 3 < NN) { int o = off0 + s2;  g_rowptr[idx + 3] = o; g_cursor[idx + 3] = o; }
        if (t == 1023) carry_sm = carry + wtot[31] + sc;
        __syncthreads();
    }
    if (t == 0) g_rowptr[NN] = EE;
}

__global__ void csr_fill_kernel(const int* __restrict__ src, const int* __restrict__ dst) {
    int e = blockIdx.x * blockDim.x + threadIdx.x;
    if (e < EE) {
        int d = dst[e];
        int pos = atomicAdd(&g_cursor[d], 1);
        g_sde[pos] = make_int4(src[e], d, e, 0);
    }
}

// ---------------- node transform: smem-staged A + direct-LDG B tf32 MMA ---------
// xl written fp16 (gather-heavy consumer), xr written fp32.
template<int OUTD, int TC>
__global__ __launch_bounds__(256) void transform_staged(
    const float* __restrict__ x, const uint2* __restrict__ Wp,
    const float* __restrict__ bl, const float* __restrict__ br,
    __half* __restrict__ xlh, float* __restrict__ xr) {
    constexpr int NTT = TC / 8;
    __shared__ unsigned xs[128 * 68];
    int tid = threadIdx.x;
    int w = tid >> 5, lane = tid & 31, g = lane >> 2, t4 = lane & 3;
    int mrow = w & 3, ncol = w >> 2;
    int node0 = blockIdx.x * 128;
    int rbase = mrow * 32;
    int ntbase = blockIdx.y * 16 + ncol * 8;

    float acc[2][8][4];
    #pragma unroll
    for (int mt = 0; mt < 2; mt++)
        #pragma unroll
        for (int nt = 0; nt < 8; nt++)
            #pragma unroll
            for (int i = 0; i < 4; i++) acc[mt][nt][i] = 0.f;

    #pragma unroll
    for (int ch = 0; ch < 2; ch++) {
        __syncthreads();
        for (int idx = tid; idx < 128 * 16; idx += 256) {
            int r = idx >> 4, q = idx & 15;
            int row = node0 + r;
            float4 v = make_float4(0.f, 0.f, 0.f, 0.f);
            if (row < NN) v = *(const float4*)&x[row * 128 + ch * 64 + q * 4];
            unsigned* p = &xs[r * 68 + q * 4];
            p[0] = tf32_of(v.x); p[1] = tf32_of(v.y);
            p[2] = tf32_of(v.z); p[3] = tf32_of(v.w);
        }
        __syncthreads();
        #pragma unroll
        for (int ktl = 0; ktl < 8; ktl++) {
            int kt = ch * 8 + ktl;
            unsigned a[2][4];
            #pragma unroll
            for (int mt = 0; mt < 2; mt++) {
                int r0 = (rbase + mt * 16 + g) * 68 + ktl * 8 + t4;
                a[mt][0] = xs[r0];
                a[mt][1] = xs[r0 + 8 * 68];
                a[mt][2] = xs[r0 + 4];
                a[mt][3] = xs[r0 + 8 * 68 + 4];
            }
            const uint2* wrow = Wp + (kt * NTT + ntbase) * 32 + lane;
            #pragma unroll
            for (int nt = 0; nt < 8; nt++) {
                uint2 b = __ldg(wrow + nt * 32);
                mma_tf32(acc[0][nt], a[0][0], a[0][1], a[0][2], a[0][3], b.x, b.y);
                mma_tf32(acc[1][nt], a[1][0], a[1][1], a[1][2], a[1][3], b.x, b.y);
            }
        }
    }

    #pragma unroll
    for (int nt = 0; nt < 8; nt++) {
        int c = (ntbase + nt) * 8 + t4 * 2;
        if (c < OUTD) {
            float2 bv = *(const float2*)&bl[c];
            #pragma unroll
            for (int mt = 0; mt < 2; mt++) {
                int n0v = node0 + rbase + mt * 16 + g;
                if (n0v < NN)
                    *(__half2*)&xlh[n0v * OUTD + c] =
                        __floats2half2_rn(acc[mt][nt][0] + bv.x, acc[mt][nt][1] + bv.y);
                int n1v = n0v + 8;
                if (n1v < NN)
                    *(__half2*)&xlh[n1v * OUTD + c] =
                        __floats2half2_rn(acc[mt][nt][2] + bv.x, acc[mt][nt][3] + bv.y);
            }
        } else {
            int cc = c - OUTD;
            float2 bv = *(const float2*)&br[cc];
            #pragma unroll
            for (int mt = 0; mt < 2; mt++) {
                int n0v = node0 + rbase + mt * 16 + g;
                if (n0v < NN)
                    *(float2*)&xr[n0v * OUTD + cc] =
                        make_float2(acc[mt][nt][0] + bv.x, acc[mt][nt][1] + bv.y);
                int n1v = n0v + 8;
                if (n1v < NN)
                    *(float2*)&xr[n1v * OUTD + cc] =
                        make_float2(acc[mt][nt][2] + bv.x, acc[mt][nt][3] + bv.y);
            }
        }
    }
}

// ---------------- layer-1 edge logits: CSR-ordered tf32 MMA ---------------------
__global__ __launch_bounds__(256) void edge_logits1_direct(
    const float* __restrict__ ea, const float* __restrict__ att) {
    int tid = threadIdx.x;
    int w = tid >> 5, lane = tid & 31, g = lane >> 2, t4 = lane & 3;
    int sbase = blockIdx.x * 128 + w * 16;

    int4 sd0 = g_sde[sbase + g];
    int4 sd1 = g_sde[sbase + 8 + g];
    int e0 = sd0.z, e1 = sd1.z;

    float d[16][4];
    #pragma unroll
    for (int nt = 0; nt < 16; nt++)
        #pragma unroll
        for (int i = 0; i < 4; i++) d[nt][i] = 0.f;

    #pragma unroll
    for (int kt = 0; kt < 4; kt++) {
        const float* p0 = ea + e0 * 32 + kt * 8 + t4;
        const float* p1 = ea + e1 * 32 + kt * 8 + t4;
        unsigned a0 = tf32_of(__ldg(p0));
        unsigned a1 = tf32_of(__ldg(p1));
        unsigned a2 = tf32_of(__ldg(p0 + 4));
        unsigned a3 = tf32_of(__ldg(p1 + 4));
        const uint2* wrow = g_We1p + (kt * 16) * 32 + lane;
        #pragma unroll
        for (int nt = 0; nt < 16; nt++) {
            uint2 b = __ldg(wrow + nt * 32);
            mma_tf32(d[nt], a0, a1, a2, a3, b.x, b.y);
        }
    }

    const __half2* xl0 = (const __half2*)(g_xl1h + sd0.x * HCD);
    const float*   xr0 = g_xr1 + sd0.y * HCD;
    const __half2* xl1r = (const __half2*)(g_xl1h + sd1.x * HCD);
    const float*   xr1r = g_xr1 + sd1.y * HCD;
    float p0h[4] = {0.f, 0.f, 0.f, 0.f};
    float p1h[4] = {0.f, 0.f, 0.f, 0.f};
    #pragma unroll
    for (int nt = 0; nt < 16; nt++) {
        int c = nt * 8 + t4 * 2;
        float2 atv = *(const float2*)&att[c];
        float2 xa = __half22float2(xl0[nt * 4 + t4]);
        float2 xb = *(const float2*)&xr0[c];
        float v0 = d[nt][0] + xa.x + xb.x;
        float v1 = d[nt][1] + xa.y + xb.y;
        p0h[nt >> 2] += lrelu(v0) * atv.x + lrelu(v1) * atv.y;
        float2 xc = __half22float2(xl1r[nt * 4 + t4]);
        float2 xd = *(const float2*)&xr1r[c];
        float u0 = d[nt][2] + xc.x + xd.x;
        float u1 = d[nt][3] + xc.y + xd.y;
        p1h[nt >> 2] += lrelu(u0) * atv.x + lrelu(u1) * atv.y;
    }
    #pragma unroll
    for (int h = 0; h < 4; h++) {
        p0h[h] += __shfl_xor_sync(0xffffffffu, p0h[h], 1);
        p0h[h] += __shfl_xor_sync(0xffffffffu, p0h[h], 2);
        p1h[h] += __shfl_xor_sync(0xffffffffu, p1h[h], 1);
        p1h[h] += __shfl_xor_sync(0xffffffffu, p1h[h], 2);
    }
    float v0 = (t4 == 0) ? p0h[0] : (t4 == 1) ? p0h[1] : (t4 == 2) ? p0h[2] : p0h[3];
    float v1 = (t4 == 0) ? p1h[0] : (t4 == 1) ? p1h[1] : (t4 == 2) ? p1h[2] : p1h[3];
    g_a1p[(sbase + g) * HEADS + t4]     = __expf(v0);
    g_a1p[(sbase + 8 + g) * HEADS + t4] = __expf(v1);
}

// ---------------- layer-2 edge logits: CSR-ordered tf32 MMA ---------------------
__global__ __launch_bounds__(256) void edge_logits2_direct(
    const float* __restrict__ ea, const float* __restrict__ att) {
    int tid = threadIdx.x;
    int w = tid >> 5, lane = tid & 31, g = lane >> 2, t4 = lane & 3;
    int sbase = blockIdx.x * 128 + w * 16;

    int4 sd0 = g_sde[sbase + g];
    int4 sd1 = g_sde[sbase + 8 + g];
    int e0 = sd0.z, e1 = sd1.z;

    float d[8][4];
    #pragma unroll
    for (int nt = 0; nt < 8; nt++)
        #pragma unroll
        for (int i = 0; i < 4; i++) d[nt][i] = 0.f;

    #pragma unroll
    for (int kt = 0; kt < 4; kt++) {
        const float* p0 = ea + e0 * 32 + kt * 8 + t4;
        const float* p1 = ea + e1 * 32 + kt * 8 + t4;
        unsigned a0 = tf32_of(__ldg(p0));
        unsigned a1 = tf32_of(__ldg(p1));
        unsigned a2 = tf32_of(__ldg(p0 + 4));
        unsigned a3 = tf32_of(__ldg(p1 + 4));
        const uint2* wrow = g_We2p + (kt * 8) * 32 + lane;
        #pragma unroll
        for (int nt = 0; nt < 8; nt++) {
            uint2 b = __ldg(wrow + nt * 32);
            mma_tf32(d[nt], a0, a1, a2, a3, b.x, b.y);
        }
    }

    const __half2* xl0 = (const __half2*)(g_xl2h + sd0.x * OUTC);
    const float*   xr0 = g_xr2 + sd0.y * OUTC;
    const __half2* xl1r = (const __half2*)(g_xl2h + sd1.x * OUTC);
    const float*   xr1r = g_xr2 + sd1.y * OUTC;
    float ps0 = 0.f, ps1 = 0.f;
    #pragma unroll
    for (int nt = 0; nt < 8; nt++) {
        int c = nt * 8 + t4 * 2;
        float2 atv = *(const float2*)&att[c];
        float2 xa = __half22float2(xl0[nt * 4 + t4]);
        float2 xb = *(const float2*)&xr0[c];
        float v0 = d[nt][0] + xa.x + xb.x;
        float v1 = d[nt][1] + xa.y + xb.y;
        ps0 += lrelu(v0) * atv.x + lrelu(v1) * atv.y;
        float2 xc = __half22float2(xl1r[nt * 4 + t4]);
        float2 xd = *(const float2*)&xr1r[c];
        float u0 = d[nt][2] + xc.x + xd.x;
        float u1 = d[nt][3] + xc.y + xd.y;
        ps1 += lrelu(u0) * atv.x + lrelu(u1) * atv.y;
    }
    ps0 += __shfl_xor_sync(0xffffffffu, ps0, 1);
    ps0 += __shfl_xor_sync(0xffffffffu, ps0, 2);
    ps1 += __shfl_xor_sync(0xffffffffu, ps1, 1);
    ps1 += __shfl_xor_sync(0xffffffffu, ps1, 2);
    if (t4 == 0) {
        g_a2p[sbase + g]     = __expf(ps0);
        g_a2p[sbase + 8 + g] = __expf(ps1);
    }
}

// ---------------- layer-1 aggregate: 2 warps/node, shuffle-broadcast ------------
__global__ void aggregate1_kernel(const float* __restrict__ bias) {
    int wi = (blockIdx.x * blockDim.x + threadIdx.x) >> 5;
    int lane = threadIdx.x & 31;
    int i = wi >> 1, half = wi & 1;
    if (i >= NN) return;
    int start = g_rowptr[i], end = g_rowptr[i + 1];
    int c0 = half * 64 + 2 * lane;
    int hsel = lane >> 4;

    float den = 0.f, a0 = 0.f, a1 = 0.f;
    for (int base = start; base < end; base += 32) {
        int n = end - base; if (n > 32) n = 32;
        float2 wv = make_float2(0.f, 0.f);
        int sv = 0;
        if (lane < n) {
            int slot = base + lane;
            wv = *(const float2*)&g_a1p[slot * HEADS + half * 2];
            sv = g_sde[slot].x;
        }
        for (int k = 0; k < n; k++) {
            float wx = __shfl_sync(0xffffffffu, wv.x, k);
            float wy = __shfl_sync(0xffffffffu, wv.y, k);
            int s = __shfl_sync(0xffffffffu, sv, k);
            float wgt = hsel ? wy : wx;
            float2 xv = __half22float2(*(const __half2*)&g_xl1h[s * HCD + c0]);
            den += wgt;
            a0 = fmaf(wgt, xv.x, a0);
            a1 = fmaf(wgt, xv.y, a1);
        }
    }
    float inv = 1.f / (den + 1e-16f);
    float2 bv = *(const float2*)&bias[c0];
    float o0 = a0 * inv + bv.x;
    float o1 = a1 * inv + bv.y;
    o0 = o0 > 0.f ? o0 : expm1f(o0);
    o1 = o1 > 0.f ? o1 : expm1f(o1);
    *(float2*)&g_h[i * HCD + c0] = make_float2(o0, o1);
}

// ---------------- layer-2 aggregate: 1 warp/node, shuffle-broadcast -------------
__global__ void aggregate2_kernel(const float* __restrict__ bias, float* __restrict__ out) {
    int i = (blockIdx.x * blockDim.x + threadIdx.x) >> 5;
    int lane = threadIdx.x & 31;
    if (i >= NN) return;
    int start = g_rowptr[i], end = g_rowptr[i + 1];
    int c0 = 2 * lane;

    float den = 0.f, a0 = 0.f, a1 = 0.f;
    for (int base = start; base < end; base += 32) {
        int n = end - base; if (n > 32) n = 32;
        float wv = 0.f;
        int sv = 0;
        if (lane < n) {
            int slot = base + lane;
            wv = g_a2p[slot];
            sv = g_sde[slot].x;
        }
        for (int k = 0; k < n; k++) {
            float wgt = __shfl_sync(0xffffffffu, wv, k);
            int s = __shfl_sync(0xffffffffu, sv, k);
            float2 xv = __half22float2(*(const __half2*)&g_xl2h[s * OUTC + c0]);
            den += wgt;
            a0 = fmaf(wgt, xv.x, a0);
            a1 = fmaf(wgt, xv.y, a1);
        }
    }
    float inv = 1.f / (den + 1e-16f);
    float o0 = a0 * inv + bias[c0];
    float o1 = a1 * inv + bias[c0 + 1];
    *(float2*)&out[i * OUTC + c0] = make_float2(o0, o1);
}

// ---------------- host launcher ---------------------------------------------------
extern "C" void kernel_launch(void* const* d_in, const int* in_sizes, int n_in,
                              void* d_out, int out_size) {
    const float* x    = (const float*)d_in[0];
    const int*   ei   = (const int*)  d_in[1];
    const float* ea   = (const float*)d_in[2];
    const float* Wl1  = (const float*)d_in[3];
    const float* bl1  = (const float*)d_in[4];
    const float* Wr1  = (const float*)d_in[5];
    const float* br1  = (const float*)d_in[6];
    const float* We1  = (const float*)d_in[7];
    const float* att1 = (const float*)d_in[8];
    const float* bias1= (const float*)d_in[9];
    const float* Wl2  = (const float*)d_in[10];
    const float* bl2  = (const float*)d_in[11];
    const float* Wr2  = (const float*)d_in[12];
    const float* br2  = (const float*)d_in[13];
    const float* We2  = (const float*)d_in[14];
    const float* att2 = (const float*)d_in[15];
    const float* bias2= (const float*)d_in[16];

    const int* src = ei;
    const int* dst = ei + EE;

    void *p_xl1h, *p_xr1, *p_h, *p_xl2h, *p_xr2, *p_deg, *p_W1p, *p_W2p;
    cudaGetSymbolAddress(&p_xl1h, g_xl1h);
    cudaGetSymbolAddress(&p_xr1, g_xr1);
    cudaGetSymbolAddress(&p_h,   g_h);
    cudaGetSymbolAddress(&p_xl2h, g_xl2h);
    cudaGetSymbolAddress(&p_xr2, g_xr2);
    cudaGetSymbolAddress(&p_deg, g_deg);
    cudaGetSymbolAddress(&p_W1p, g_W1p);
    cudaGetSymbolAddress(&p_W2p, g_W2p);

    // one-time host-side stream/event objects (no device memory involved)
    static cudaStream_t s_csr = nullptr;
    static cudaEvent_t ev_fork = nullptr, ev_csr_done = nullptr;
    if (s_csr == nullptr) {
        cudaStreamCreateWithFlags(&s_csr, cudaStreamNonBlocking);
        cudaEventCreateWithFlags(&ev_fork, cudaEventDisableTiming);
        cudaEventCreateWithFlags(&ev_csr_done, cudaEventDisableTiming);
    }

    // fork: CSR branch on s_csr, weight-prep + transform1 on main stream
    cudaEventRecord(ev_fork, 0);
    cudaStreamWaitEvent(s_csr, ev_fork, 0);

    // --- CSR branch (side stream) ---
    cudaMemsetAsync(p_deg, 0, NN * sizeof(int), s_csr);
    csr_count_kernel<<<(EE / 4 + 255) / 256, 256, 0, s_csr>>>(dst);
    scan_kernel<<<1, 1024, 0, s_csr>>>();
    csr_fill_kernel<<<(EE + 255) / 256, 256, 0, s_csr>>>(src, dst);
    cudaEventRecord(ev_csr_done, s_csr);

    // --- main branch ---
    prepack_kernel<<<108, 256>>>(Wl1, Wr1, Wl2, Wr2, We1, We2);
    transform_staged<HCD, 256><<<dim3((NN + 127) / 128, 2), 256>>>(
        x, (const uint2*)p_W1p, bl1, br1, (__half*)p_xl1h, (float*)p_xr1);

    // join: logits1 needs CSR + transform1 + prepack
    cudaStreamWaitEvent(0, ev_csr_done, 0);

    edge_logits1_direct<<<EE / 128, 256>>>(ea, att1);
    aggregate1_kernel<<<(2 * NN + 7) / 8, 256>>>(bias1);

    // layer 2
    transform_staged<OUTC, 128><<<dim3((NN + 127) / 128, 1), 256>>>(
        (const float*)p_h, (const uint2*)p_W2p, bl2, br2, (__half*)p_xl2h, (float*)p_xr2);
    edge_logits2_direct<<<EE / 128, 256>>>(ea, att2);
    aggregate2_kernel<<<NN / 8, 256>>>(bias2, (float*)d_out);
}